// round 10
// baseline (speedup 1.0000x reference)
#include <cuda_runtime.h>
#include <cuda_bf16.h>
#include <cstdint>
#include <math.h>

#define BATCH 8
#define SEQ 512
#define DMODEL 512
#define NHEAD 8
#define DHEAD 64
#define DFF 2048
#define NLAYER 6
#define DIN 64
#define MTOK (BATCH*SEQ)
#define BH (BATCH*NHEAD)
typedef __nv_bfloat16 bf16;

#define TROW 80    // 32 bf16 (64B) + 16B pad; ldsm rows hit disjoint bank quads

__device__ __forceinline__ uint32_t smem_u32(const void* p){
    uint32_t a; asm("{ .reg .u64 t; cvta.to.shared.u64 t, %1; cvt.u32.u64 %0, t; }":"=r"(a):"l"(p)); return a;
}
__device__ __forceinline__ void ldsm4(uint32_t* r, uint32_t a){
    asm volatile("ldmatrix.sync.aligned.m8n8.x4.shared.b16 {%0,%1,%2,%3}, [%4];"
        : "=r"(r[0]),"=r"(r[1]),"=r"(r[2]),"=r"(r[3]) : "r"(a));
}
__device__ __forceinline__ void mma16816(float* d, const uint32_t* a, const uint32_t* b){
    asm volatile("mma.sync.aligned.m16n8k16.row.col.f32.bf16.bf16.f32 "
        "{%0,%1,%2,%3}, {%4,%5,%6,%7}, {%8,%9}, {%0,%1,%2,%3};"
        : "+f"(d[0]),"+f"(d[1]),"+f"(d[2]),"+f"(d[3])
        : "r"(a[0]),"r"(a[1]),"r"(a[2]),"r"(a[3]),"r"(b[0]),"r"(b[1]));
}
__device__ __forceinline__ void split2(float f, bf16&h, bf16&l){
    h=__float2bfloat16(f); l=__float2bfloat16(f-__bfloat162float(h));
}
#define CP16(dst,src) asm volatile("cp.async.cg.shared.global [%0], [%1], 16;"::"r"(dst),"l"(src))
#define CP_COMMIT() asm volatile("cp.async.commit_group;":::"memory")
#define CP_WAIT0() asm volatile("cp.async.wait_group 0;":::"memory")
#define CP_WAIT1() asm volatile("cp.async.wait_group 1;":::"memory")

// ---------- scratch ----------
__device__ float g_pe[SEQ*DMODEL];
__device__ float g_x[MTOK*DMODEL];
__device__ float g_tmp[MTOK*DMODEL];
__device__ float g_sumr[BH*SEQ];
__device__ float g_sc[(size_t)BH*SEQ*SEQ];
__device__ float g_bqkv[NLAYER*1536];
__device__ bf16 g_srch[MTOK*DIN], g_srcl[MTOK*DIN];
__device__ bf16 g_xh[MTOK*DMODEL], g_xl[MTOK*DMODEL];
__device__ bf16 g_qkh[2*MTOK*DMODEL], g_qkl[2*MTOK*DMODEL];
__device__ bf16 g_vth[BH*DHEAD*SEQ], g_vtl[BH*DHEAD*SEQ];
__device__ bf16 g_ch[MTOK*DMODEL], g_cl[MTOK*DMODEL];
__device__ bf16 g_fh[MTOK*DFF], g_fl[MTOK*DFF];
__device__ bf16 g_ph[(size_t)BH*SEQ*SEQ], g_pl[(size_t)BH*SEQ*SEQ];
__device__ bf16 g_fw1h[DFF*DIN], g_fw1l[DFF*DIN];
__device__ bf16 g_fw2h[DMODEL*DFF], g_fw2l[DMODEL*DFF];
__device__ bf16 g_wqkvh[NLAYER*1536*DMODEL], g_wqkvl[NLAYER*1536*DMODEL];
__device__ bf16 g_woh[NLAYER*DMODEL*DMODEL], g_wolo[NLAYER*DMODEL*DMODEL];
__device__ bf16 g_f1h[NLAYER*DFF*DMODEL], g_f1l[NLAYER*DFF*DMODEL];
__device__ bf16 g_f2h[NLAYER*DMODEL*DFF], g_f2l[NLAYER*DMODEL*DFF];

// ---------- weight transpose+split ----------
__device__ __forceinline__ void do_tsplit(const float* __restrict__ W, bf16* __restrict__ Oh,
                                          bf16* __restrict__ Ol, int K, int N, int z, int bx, int by,
                                          size_t lstride){
    __shared__ float t[32][33];
    const float* w=W+(size_t)z*K*N;
    bf16* oh=Oh+(size_t)z*lstride; bf16* ol=Ol+(size_t)z*lstride;
    int n0=bx*32, k0=by*32, tx=threadIdx.x, ty=threadIdx.y;
#pragma unroll
    for(int i=0;i<32;i+=8) t[ty+i][tx]=w[(size_t)(k0+ty+i)*N+n0+tx];
    __syncthreads();
#pragma unroll
    for(int i=0;i<32;i+=8){
        bf16 h,l; split2(t[tx][ty+i],h,l);
        oh[(size_t)(n0+ty+i)*K+k0+tx]=h; ol[(size_t)(n0+ty+i)*K+k0+tx]=l;
    }
}
#define QKVSTRIDE ((size_t)1536*DMODEL)
__global__ void tsplit_all(const float* fin_w1, const float* fin_w2,
    const float* wq, const float* wk, const float* wv, const float* wo,
    const float* ffw1, const float* ffw2,
    bf16* fw1h, bf16* fw1l, bf16* fw2h, bf16* fw2l,
    bf16* wqkvh, bf16* wqkvl, bf16* woh, bf16* wolo,
    bf16* f1h, bf16* f1l, bf16* f2h, bf16* f2l){
    int bid=blockIdx.x;
    if(bid<128){ int i=bid; do_tsplit(fin_w1,fw1h,fw1l,DIN,DFF,0,i%64,i/64,0); return; } bid-=128;
    if(bid<1024){ int i=bid; do_tsplit(fin_w2,fw2h,fw2l,DFF,DMODEL,0,i%16,i/16,0); return; } bid-=1024;
    if(bid<1536){ int i=bid; do_tsplit(wq,wqkvh,        wqkvl,        DMODEL,DMODEL,i/256,(i%256)%16,(i%256)/16,QKVSTRIDE); return; } bid-=1536;
    if(bid<1536){ int i=bid; do_tsplit(wk,wqkvh+262144, wqkvl+262144, DMODEL,DMODEL,i/256,(i%256)%16,(i%256)/16,QKVSTRIDE); return; } bid-=1536;
    if(bid<1536){ int i=bid; do_tsplit(wv,wqkvh+524288, wqkvl+524288, DMODEL,DMODEL,i/256,(i%256)%16,(i%256)/16,QKVSTRIDE); return; } bid-=1536;
    if(bid<1536){ int i=bid; do_tsplit(wo,woh,wolo,DMODEL,DMODEL,i/256,(i%256)%16,(i%256)/16,(size_t)DMODEL*DMODEL); return; } bid-=1536;
    if(bid<6144){ int i=bid; do_tsplit(ffw1,f1h,f1l,DMODEL,DFF,i/1024,(i%1024)%64,(i%1024)/64,(size_t)DMODEL*DFF); return; } bid-=6144;
    { int i=bid; do_tsplit(ffw2,f2h,f2l,DFF,DMODEL,i/1024,(i%1024)%16,(i%1024)/16,(size_t)DMODEL*DFF); }
}
#define TSPLIT_BLOCKS (128+1024+4*1536+6144+6144)

#define SRCBLK ((MTOK*DIN+255)/256)
__global__ void prep_misc(float* __restrict__ pe, const float* __restrict__ src,
                          bf16* __restrict__ sh, bf16* __restrict__ sl,
                          const float* __restrict__ bq, const float* __restrict__ bk,
                          const float* __restrict__ bv, float* __restrict__ bqkv){
    int bid=blockIdx.x, t=threadIdx.x;
    if(bid<SEQ){
        float dv=expf(-(float)(2*t)*(logf(10000.0f)/(float)DMODEL));
        float a=(float)bid*dv;
        pe[bid*DMODEL+2*t]=sinf(a); pe[bid*DMODEL+2*t+1]=cosf(a);
    } else if(bid<SEQ+SRCBLK){
        int i=(bid-SEQ)*256+t;
        if(i<MTOK*DIN){ bf16 h,l; split2(src[i],h,l); sh[i]=h; sl[i]=l; }
    } else {
        int i=(bid-SEQ-SRCBLK)*256+t;
        if(i<NLAYER*1536){
            int l=i/1536, r=i%1536;
            float v = r<512 ? bq[l*512+r] : (r<1024 ? bk[l*512+r-512] : bv[l*512+r-1024]);
            bqkv[i]=v;
        }
    }
}
#define PREP_BLOCKS (SEQ + SRCBLK + (NLAYER*1536+255)/256)

// ---------- cp.async loader: nrows x 32 bf16 into TROW-stride smem ----------
__device__ __forceinline__ void load_cp(uint32_t dst, const bf16* __restrict__ src,
                                        int row0, int k0, int ld, int nrows){
    for(int idx=threadIdx.x; idx<nrows*4; idx+=256){
        int r=idx>>2, c=idx&3;
        CP16(dst + r*TROW + c*16, src + (size_t)(row0+r)*ld + k0 + c*8);
    }
}

// one K-chunk (KK k16 steps) of bf16x3 mma, term-major
template<int MI,int NI,int KK>
__device__ __forceinline__ void mma_chunk(uint32_t sa, uint32_t sal, uint32_t sb, uint32_t sbl,
                                          float (*acc)[4], int lane, int wm, int wn){
    int ar=(lane&7)+((lane>>3)&1)*8, abit=((lane>>4)&1)*8;
    int br=(lane&7)+((lane>>4)&1)*8, bbit=((lane>>3)&1)*8;
#pragma unroll
    for(int kk=0;kk<KK;kk++){
        uint32_t ah[MI][4], al[MI][4], bh[NI][2], bl[NI][2];
        int ac=kk*16+abit, bc=kk*16+bbit;
#pragma unroll
        for(int mi=0;mi<MI;mi++){
            uint32_t off=(uint32_t)((wm+mi*16+ar)*TROW + ac*2);
            ldsm4(ah[mi], sa+off); ldsm4(al[mi], sal+off);
        }
#pragma unroll
        for(int nj=0;nj<NI/2;nj++){
            uint32_t off=(uint32_t)((wn+nj*16+br)*TROW + bc*2);
            uint32_t r[4];
            ldsm4(r, sb+off);  bh[nj*2][0]=r[0]; bh[nj*2][1]=r[1]; bh[nj*2+1][0]=r[2]; bh[nj*2+1][1]=r[3];
            ldsm4(r, sbl+off); bl[nj*2][0]=r[0]; bl[nj*2][1]=r[1]; bl[nj*2+1][0]=r[2]; bl[nj*2+1][1]=r[3];
        }
#pragma unroll
        for(int mi=0;mi<MI;mi++)
#pragma unroll
            for(int ni=0;ni<NI;ni++) mma16816(acc[mi*NI+ni], ah[mi], bh[ni]);
#pragma unroll
        for(int mi=0;mi<MI;mi++)
#pragma unroll
            for(int ni=0;ni<NI;ni++) mma16816(acc[mi*NI+ni], al[mi], bh[ni]);
#pragma unroll
        for(int mi=0;mi<MI;mi++)
#pragma unroll
            for(int ni=0;ni<NI;ni++) mma16816(acc[mi*NI+ni], ah[mi], bl[ni]);
    }
}

// ---------- GEMM: tile 64x128, K-chunk 32, 3-stage, ONE barrier/chunk, 2 CTAs/SM ----
// stage: A=0(5120) AL=5120 B=10240(10240) BL=20480... offsets below; STG=30720
#define GASZ (64*TROW)      // 5120
#define GBSZ (128*TROW)     // 10240
#define GSTG (2*GASZ+2*GBSZ) // 30720
#define GSMEM3 (3*GSTG)      // 92160
// epi: 1 bias,relu->hi/lo | 3 bias->f32 | 4 bias,*alpha,+pe->f32+hi/lo | 5 fused QKV
__global__ __launch_bounds__(256,2)
void gemm_bf3(const bf16* __restrict__ Ah, const bf16* __restrict__ Al, int lda,
              const bf16* __restrict__ Bh, const bf16* __restrict__ Bl, int K,
              const float* __restrict__ bias, int epi,
              float* __restrict__ of, bf16* __restrict__ oh, bf16* __restrict__ ol,
              bf16* __restrict__ vh, bf16* __restrict__ vl,
              int ldc, float alpha, const float* __restrict__ pe){
    extern __shared__ char smem[];
    uint32_t sb0=smem_u32(smem);
    int tid=threadIdx.x, wid=tid>>5, lane=tid&31;
    int row0=blockIdx.y*64, col0=blockIdx.x*128;
    int wm=(wid>>2)*32, wn=(wid&3)*32;
    float acc[8][4];
#pragma unroll
    for(int i=0;i<8;i++){ acc[i][0]=0;acc[i][1]=0;acc[i][2]=0;acc[i][3]=0; }
    int NC=K/32;
    // prologue: chunks 0,1 into stages 0,1
#pragma unroll
    for(int c0=0;c0<2;c0++){
        uint32_t s=sb0+c0*GSTG;
        load_cp(s,             Ah,row0,c0*32,lda,64);
        load_cp(s+GASZ,        Al,row0,c0*32,lda,64);
        load_cp(s+2*GASZ,      Bh,col0,c0*32,K,128);
        load_cp(s+2*GASZ+GBSZ, Bl,col0,c0*32,K,128);
        CP_COMMIT();
    }
    int st=0;
    for(int kc=0;kc<NC;kc++){
        if(kc+1<NC) CP_WAIT1(); else CP_WAIT0();
        __syncthreads();
        if(kc+2<NC){
            int s2=st+2; if(s2>=3) s2-=3;
            uint32_t s=sb0+s2*GSTG;
            int k0=(kc+2)*32;
            load_cp(s,             Ah,row0,k0,lda,64);
            load_cp(s+GASZ,        Al,row0,k0,lda,64);
            load_cp(s+2*GASZ,      Bh,col0,k0,K,128);
            load_cp(s+2*GASZ+GBSZ, Bl,col0,k0,K,128);
            CP_COMMIT();
        }
        uint32_t s=sb0+st*GSTG;
        mma_chunk<2,4,2>(s,s+GASZ,s+2*GASZ,s+2*GASZ+GBSZ,acc,lane,wm,wn);
        if(++st==3) st=0;
    }
    int gid=lane>>2, tig=lane&3;
#pragma unroll
    for(int mi=0;mi<2;mi++)
#pragma unroll
    for(int ni=0;ni<4;ni++){
        float* d=acc[mi*4+ni];
#pragma unroll
        for(int hf=0;hf<2;hf++){
            int r=row0+wm+mi*16+gid+hf*8;
            int c=col0+wn+ni*8+tig*2;
            float v0=d[hf*2]+__ldg(&bias[c]), v1=d[hf*2+1]+__ldg(&bias[c+1]);
            if(epi==1){ v0=fmaxf(v0,0.f); v1=fmaxf(v1,0.f); }
            if(epi==4){
                const float* per=pe+(size_t)(r&(SEQ-1))*DMODEL+c;
                v0=v0*alpha+per[0]; v1=v1*alpha+per[1];
            }
            if(epi==3||epi==4) *(float2*)(of+(size_t)r*ldc+c)=make_float2(v0,v1);
            if(epi==1||epi==4){
                bf16 h0,l0,h1,l1; split2(v0,h0,l0); split2(v1,h1,l1);
                __nv_bfloat162 H{h0,h1}, L{l0,l1};
                *(__nv_bfloat162*)(oh+(size_t)r*ldc+c)=H;
                *(__nv_bfloat162*)(ol+(size_t)r*ldc+c)=L;
            }
            if(epi==5){
                if(c<1024){
                    size_t off=(size_t)(c>>9)*((size_t)MTOK*DMODEL)+(size_t)r*DMODEL+(c&511);
                    bf16 h0,l0,h1,l1; split2(v0,h0,l0); split2(v1,h1,l1);
                    __nv_bfloat162 H{h0,h1}, L{l0,l1};
                    *(__nv_bfloat162*)(oh+off)=H; *(__nv_bfloat162*)(ol+off)=L;
                } else {
                    int b=r>>9, s=r&(SEQ-1);
#pragma unroll
                    for(int u=0;u<2;u++){
                        int n=(c&511)+u; float v=u?v1:v0;
                        size_t off=((size_t)(b*NHEAD+(n>>6))*DHEAD+(n&63))*SEQ+s;
                        bf16 hh,ll; split2(v,hh,ll); vh[off]=hh; vl[off]=ll;
                    }
                }
            }
        }
    }
}

// ---------- QK^T -> f32 scores. K=64 = two chunk-32 loads upfront. grid(4,4,BH) ----
#define QASZ (128*TROW)     // 10240
#define QSTG (4*QASZ)       // 40960
#define QSMEM (2*QSTG)      // 81920
__global__ __launch_bounds__(256,2)
void qk_kernel(const bf16* __restrict__ qh, const bf16* __restrict__ ql,
               const bf16* __restrict__ kh, const bf16* __restrict__ kl,
               float* __restrict__ sc, float scale){
    extern __shared__ char smem[];
    uint32_t sb0=smem_u32(smem);
    int tid=threadIdx.x, wid=tid>>5, lane=tid&31;
    int z=blockIdx.z, b=z>>3, h=z&7;
    int row0=blockIdx.y*128, col0=blockIdx.x*128, k0=h*DHEAD;
    int wm=(wid>>2)*64, wn=(wid&3)*32;
    float acc[16][4];
#pragma unroll
    for(int i=0;i<16;i++){ acc[i][0]=0;acc[i][1]=0;acc[i][2]=0;acc[i][3]=0; }
#pragma unroll
    for(int cc=0;cc<2;cc++){
        uint32_t s=sb0+cc*QSTG;
        load_cp(s,        qh,b*SEQ+row0,k0+cc*32,DMODEL,128);
        load_cp(s+QASZ,   ql,b*SEQ+row0,k0+cc*32,DMODEL,128);
        load_cp(s+2*QASZ, kh,b*SEQ+col0,k0+cc*32,DMODEL,128);
        load_cp(s+3*QASZ, kl,b*SEQ+col0,k0+cc*32,DMODEL,128);
        CP_COMMIT();
    }
    CP_WAIT0();
    __syncthreads();
#pragma unroll
    for(int cc=0;cc<2;cc++){
        uint32_t s=sb0+cc*QSTG;
        mma_chunk<4,4,2>(s,s+QASZ,s+2*QASZ,s+3*QASZ,acc,lane,wm,wn);
    }
    int gid=lane>>2, tig=lane&3;
    float* eb=sc+(size_t)z*SEQ*SEQ;
#pragma unroll
    for(int mi=0;mi<4;mi++)
#pragma unroll
    for(int ni=0;ni<4;ni++){
        float* d=acc[mi*4+ni];
#pragma unroll
        for(int hf=0;hf<2;hf++){
            int r=row0+wm+mi*16+gid+hf*8, c=col0+wn+ni*8+tig*2;
            *(float2*)(eb+(size_t)r*SEQ+c)=make_float2(d[hf*2]*scale,d[hf*2+1]*scale);
        }
    }
}

// ---------- softmax -> unnormalized exp hi/lo + 1/sum ----------
__global__ __launch_bounds__(128)
void softmax_kernel(const float* __restrict__ sc, bf16* __restrict__ ph, bf16* __restrict__ pl,
                    float* __restrict__ sumr){
    __shared__ float red[128];
    int row=blockIdx.x, t=threadIdx.x;
    const float4* p=(const float4*)(sc+(size_t)row*SEQ);
    float4 v=p[t];
    float m=fmaxf(fmaxf(v.x,v.y),fmaxf(v.z,v.w));
    red[t]=m; __syncthreads();
    for(int s=64;s>0;s>>=1){ if(t<s) red[t]=fmaxf(red[t],red[t+s]); __syncthreads(); }
    m=red[0]; __syncthreads();
    float e0=__expf(v.x-m), e1=__expf(v.y-m), e2=__expf(v.z-m), e3=__expf(v.w-m);
    red[t]=e0+e1+e2+e3; __syncthreads();
    for(int s=64;s>0;s>>=1){ if(t<s) red[t]+=red[t+s]; __syncthreads(); }
    if(t==0) sumr[row]=1.0f/red[0];
    size_t off=(size_t)row*SEQ+t*4;
    bf16 h0,l0,h1,l1,h2,l2,h3,l3;
    split2(e0,h0,l0); split2(e1,h1,l1); split2(e2,h2,l2); split2(e3,h3,l3);
    __nv_bfloat162 H0{h0,h1},H1{h2,h3},L0{l0,l1},L1{l2,l3};
    *(__nv_bfloat162*)(ph+off)=H0; *(__nv_bfloat162*)(ph+off+2)=H1;
    *(__nv_bfloat162*)(pl+off)=L0; *(__nv_bfloat162*)(pl+off+2)=L1;
}

// ---------- attn @ V, K-chunk 32, 3-stage, one barrier/chunk. grid(4,BH) ----------
#define AASZ (128*TROW)      // 10240 (P tile)
#define ABSZ (64*TROW)       // 5120  (V^T tile)
#define ASTG (2*AASZ+2*ABSZ) // 30720
#define ASMEM3 (3*ASTG)      // 92160
__global__ __launch_bounds__(256,2)
void av_bf3(const bf16* __restrict__ ph, const bf16* __restrict__ pl,
            const bf16* __restrict__ vth, const bf16* __restrict__ vtl,
            const float* __restrict__ sumr, bf16* __restrict__ ch, bf16* __restrict__ cl){
    extern __shared__ char smem[];
    uint32_t sb0=smem_u32(smem);
    int tid=threadIdx.x, wid=tid>>5, lane=tid&31;
    int z=blockIdx.y, b=z>>3, h=z&7;
    int row0=blockIdx.x*128;
    int wm=(wid>>2)*64, wn=(wid&3)*16;
    float acc[8][4];
#pragma unroll
    for(int i=0;i<8;i++){ acc[i][0]=0;acc[i][1]=0;acc[i][2]=0;acc[i][3]=0; }
    const bf16* pbh=ph+(size_t)z*SEQ*SEQ;
    const bf16* pbl=pl+(size_t)z*SEQ*SEQ;
#pragma unroll
    for(int c0=0;c0<2;c0++){
        uint32_t s=sb0+c0*ASTG;
        load_cp(s,             pbh,row0,c0*32,SEQ,128);
        load_cp(s+AASZ,        pbl,row0,c0*32,SEQ,128);
        load_cp(s+2*AASZ,      vth,z*DHEAD,c0*32,SEQ,64);
        load_cp(s+2*AASZ+ABSZ, vtl,z*DHEAD,c0*32,SEQ,64);
        CP_COMMIT();
    }
    int st=0;
    for(int kc=0;kc<16;kc++){
        if(kc+1<16) CP_WAIT1(); else CP_WAIT0();
        __syncthreads();
        if(kc+2<16){
            int s2=st+2; if(s2>=3) s2-=3;
            uint32_t s=sb0+s2*ASTG;
            int k0=(kc+2)*32;
            load_cp(s,             pbh,row0,k0,SEQ,128);
            load_cp(s+AASZ,        pbl,row0,k0,SEQ,128);
            load_cp(s+2*AASZ,      vth,z*DHEAD,k0,SEQ,64);
            load_cp(s+2*AASZ+ABSZ, vtl,z*DHEAD,k0,SEQ,64);
            CP_COMMIT();
        }
        uint32_t s=sb0+st*ASTG;
        mma_chunk<4,2,2>(s,s+AASZ,s+2*AASZ,s+2*AASZ+ABSZ,acc,lane,wm,wn);
        if(++st==3) st=0;
    }
    int gid=lane>>2, tig=lane&3;
#pragma unroll
    for(int mi=0;mi<4;mi++)
#pragma unroll
    for(int ni=0;ni<2;ni++){
        float* d=acc[mi*2+ni];
#pragma unroll
        for(int hf=0;hf<2;hf++){
            int rl=row0+wm+mi*16+gid+hf*8;
            float inv=sumr[(size_t)z*SEQ+rl];
            int token=b*SEQ+rl, c=wn+ni*8+tig*2;
            float v0=d[hf*2]*inv, v1=d[hf*2+1]*inv;
            bf16 h0,l0,h1,l1; split2(v0,h0,l0); split2(v1,h1,l1);
            __nv_bfloat162 H{h0,h1}, L{l0,l1};
            size_t off=(size_t)token*DMODEL+h*DHEAD+c;
            *(__nv_bfloat162*)(ch+off)=H; *(__nv_bfloat162*)(cl+off)=L;
        }
    }
}

// ---------- residual + LN -> f32 + hi/lo ----------
__global__ __launch_bounds__(128)
void ln_kernel(const float* __restrict__ x, const float* __restrict__ res,
               const float* __restrict__ gs, const float* __restrict__ gb,
               float* __restrict__ out, bf16* __restrict__ oh, bf16* __restrict__ ol){
    __shared__ float red[128];
    int row=blockIdx.x, t=threadIdx.x;
    float4 a=*(const float4*)&x[(size_t)row*DMODEL+t*4];
    float4 r=*(const float4*)&res[(size_t)row*DMODEL+t*4];
    float y0=a.x+r.x, y1=a.y+r.y, y2=a.z+r.z, y3=a.w+r.w;
    red[t]=y0+y1+y2+y3; __syncthreads();
    for(int s=64;s>0;s>>=1){ if(t<s) red[t]+=red[t+s]; __syncthreads(); }
    float mu=red[0]*(1.0f/DMODEL); __syncthreads();
    float d0=y0-mu,d1=y1-mu,d2=y2-mu,d3=y3-mu;
    red[t]=d0*d0+d1*d1+d2*d2+d3*d3; __syncthreads();
    for(int s=64;s>0;s>>=1){ if(t<s) red[t]+=red[t+s]; __syncthreads(); }
    float k=rsqrtf(red[0]*(1.0f/DMODEL)+1e-5f);
    float4 sv=*(const float4*)&gs[t*4], bv=*(const float4*)&gb[t*4];
    float o0=d0*k*sv.x+bv.x, o1=d1*k*sv.y+bv.y, o2=d2*k*sv.z+bv.z, o3=d3*k*sv.w+bv.w;
    *(float4*)&out[(size_t)row*DMODEL+t*4]=make_float4(o0,o1,o2,o3);
    size_t off=(size_t)row*DMODEL+t*4;
    bf16 h0,l0,h1,l1,h2,l2,h3,l3;
    split2(o0,h0,l0); split2(o1,h1,l1); split2(o2,h2,l2); split2(o3,h3,l3);
    __nv_bfloat162 H0{h0,h1},H1{h2,h3},L0{l0,l1},L1{l2,l3};
    *(__nv_bfloat162*)(oh+off)=H0; *(__nv_bfloat162*)(oh+off+2)=H1;
    *(__nv_bfloat162*)(ol+off)=L0; *(__nv_bfloat162*)(ol+off+2)=L1;
}

// ---------- host ----------
#define GETP(sym,p,T) do{ void* _t; cudaGetSymbolAddress(&_t,sym); p=(T*)_t; }while(0)

extern "C" void kernel_launch(void* const* d_in, const int* in_sizes, int n_in,
                              void* d_out, int out_size){
    const float* source=(const float*)d_in[0];
    const float* fin_w1=(const float*)d_in[2];
    const float* fin_b1=(const float*)d_in[3];
    const float* fin_w2=(const float*)d_in[4];
    const float* fin_b2=(const float*)d_in[5];
    const float* wq=(const float*)d_in[6];  const float* bq=(const float*)d_in[7];
    const float* wk=(const float*)d_in[8];  const float* bk=(const float*)d_in[9];
    const float* wv=(const float*)d_in[10]; const float* bvv=(const float*)d_in[11];
    const float* wo=(const float*)d_in[12]; const float* bo=(const float*)d_in[13];
    const float* n1s=(const float*)d_in[14]; const float* n1b=(const float*)d_in[15];
    const float* ffw1=(const float*)d_in[16]; const float* ffb1=(const float*)d_in[17];
    const float* ffw2=(const float*)d_in[18]; const float* ffb2=(const float*)d_in[19];
    const float* n2s=(const float*)d_in[20]; const float* n2b=(const float*)d_in[21];
    float* out=(float*)d_out;

    float *ppe,*px,*ptmp,*psumr,*psc,*pbqkv;
    GETP(g_pe,ppe,float); GETP(g_x,px,float); GETP(g_tmp,ptmp,float);
    GETP(g_sumr,psumr,float); GETP(g_sc,psc,float); GETP(g_bqkv,pbqkv,float);
    bf16 *srch,*srcl,*xh,*xl,*qkh,*qkl,*vth,*vtl,*chh,*cll,*fhh,*fll,*phh,*pll;
    GETP(g_srch,srch,bf16); GETP(g_srcl,srcl,bf16);
    GETP(g_xh,xh,bf16); GETP(g_xl,xl,bf16);
    GETP(g_qkh,qkh,bf16); GETP(g_qkl,qkl,bf16);
    GETP(g_vth,vth,bf16); GETP(g_vtl,vtl,bf16);
    GETP(g_ch,chh,bf16); GETP(g_cl,cll,bf16);
    GETP(g_fh,fhh,bf16); GETP(g_fl,fll,bf16);
    GETP(g_ph,phh,bf16); GETP(g_pl,pll,bf16);
    bf16 *fw1h,*fw1l,*fw2h,*fw2l,*wqkvh,*wqkvl,*woh,*wolo,*f1h,*f1l,*f2h,*f2l;
    GETP(g_fw1h,fw1h,bf16); GETP(g_fw1l,fw1l,bf16);
    GETP(g_fw2h,fw2h,bf16); GETP(g_fw2l,fw2l,bf16);
    GETP(g_wqkvh,wqkvh,bf16); GETP(g_wqkvl,wqkvl,bf16);
    GETP(g_woh,woh,bf16); GETP(g_wolo,wolo,bf16);
    GETP(g_f1h,f1h,bf16); GETP(g_f1l,f1l,bf16);
    GETP(g_f2h,f2h,bf16); GETP(g_f2l,f2l,bf16);

    cudaFuncSetAttribute(gemm_bf3,  cudaFuncAttributeMaxDynamicSharedMemorySize, GSMEM3);
    cudaFuncSetAttribute(qk_kernel, cudaFuncAttributeMaxDynamicSharedMemorySize, QSMEM);
    cudaFuncSetAttribute(av_bf3,    cudaFuncAttributeMaxDynamicSharedMemorySize, ASMEM3);

    const float sqrtd=22.627416998f, scale=0.044194173824f;

    tsplit_all<<<TSPLIT_BLOCKS, dim3(32,8)>>>(fin_w1,fin_w2,wq,wk,wv,wo,ffw1,ffw2,
        fw1h,fw1l,fw2h,fw2l,wqkvh,wqkvl,woh,wolo,f1h,f1l,f2h,f2l);
    prep_misc<<<PREP_BLOCKS,256>>>(ppe,source,srch,srcl,bq,bk,bvv,pbqkv);

    // input FFN
    gemm_bf3<<<dim3(16,64),256,GSMEM3>>>(srch,srcl,DIN,fw1h,fw1l,DIN,fin_b1,1,
        nullptr,fhh,fll,nullptr,nullptr,DFF,0.f,nullptr);
    gemm_bf3<<<dim3(4,64),256,GSMEM3>>>(fhh,fll,DFF,fw2h,fw2l,DFF,fin_b2,4,
        px,xh,xl,nullptr,nullptr,DMODEL,sqrtd,ppe);

    for(int l=0;l<NLAYER;l++){
        size_t w5=(size_t)l*DMODEL*DMODEL;
        size_t wqkv=(size_t)l*1536*DMODEL;
        size_t wf1=(size_t)l*DFF*DMODEL, wf2=(size_t)l*DMODEL*DFF;

        gemm_bf3<<<dim3(12,64),256,GSMEM3>>>(xh,xl,DMODEL,wqkvh+wqkv,wqkvl+wqkv,DMODEL,
            pbqkv+l*1536,5,nullptr,qkh,qkl,vth,vtl,DMODEL,0.f,nullptr);

        qk_kernel<<<dim3(4,4,BH),256,QSMEM>>>(qkh,qkl,qkh+(size_t)MTOK*DMODEL,qkl+(size_t)MTOK*DMODEL,psc,scale);
        softmax_kernel<<<BH*SEQ,128>>>(psc,phh,pll,psumr);
        av_bf3<<<dim3(4,BH),256,ASMEM3>>>(phh,pll,vth,vtl,psumr,chh,cll);

        gemm_bf3<<<dim3(4,64),256,GSMEM3>>>(chh,cll,DMODEL,woh+w5,wolo+w5,DMODEL,bo+l*DMODEL,3,
            ptmp,nullptr,nullptr,nullptr,nullptr,DMODEL,0.f,nullptr);
        ln_kernel<<<MTOK,128>>>(px,ptmp,n1s+l*DMODEL,n1b+l*DMODEL,px,xh,xl);

        gemm_bf3<<<dim3(16,64),256,GSMEM3>>>(xh,xl,DMODEL,f1h+wf1,f1l+wf1,DMODEL,ffb1+l*DFF,1,
            nullptr,fhh,fll,nullptr,nullptr,DFF,0.f,nullptr);
        gemm_bf3<<<dim3(4,64),256,GSMEM3>>>(fhh,fll,DFF,f2h+wf2,f2l+wf2,DFF,ffb2+l*DMODEL,3,
            ptmp,nullptr,nullptr,nullptr,nullptr,DMODEL,0.f,nullptr);

        float* lnout=(l==NLAYER-1)?out:px;
        ln_kernel<<<MTOK,128>>>(px,ptmp,n2s+l*DMODEL,n2b+l*DMODEL,lnout,xh,xl);
    }
}

// round 11
// speedup vs baseline: 1.3572x; 1.3572x over previous
#include <cuda_runtime.h>
#include <cuda_fp16.h>
#include <cstdint>
#include <math.h>

#define BATCH 8
#define SEQ 512
#define DMODEL 512
#define NHEAD 8
#define DHEAD 64
#define DFF 2048
#define NLAYER 6
#define DIN 64
#define MTOK (BATCH*SEQ)
#define BH (BATCH*NHEAD)
typedef __half f16;

#define TROW 144   // 72 f16/row, conflict-free ldmatrix

__device__ __forceinline__ uint32_t smem_u32(const void* p){
    uint32_t a; asm("{ .reg .u64 t; cvta.to.shared.u64 t, %1; cvt.u32.u64 %0, t; }":"=r"(a):"l"(p)); return a;
}
__device__ __forceinline__ void ldsm4(uint32_t* r, uint32_t a){
    asm volatile("ldmatrix.sync.aligned.m8n8.x4.shared.b16 {%0,%1,%2,%3}, [%4];"
        : "=r"(r[0]),"=r"(r[1]),"=r"(r[2]),"=r"(r[3]) : "r"(a));
}
__device__ __forceinline__ void mma16816(float* d, const uint32_t* a, const uint32_t* b){
    asm volatile("mma.sync.aligned.m16n8k16.row.col.f32.f16.f16.f32 "
        "{%0,%1,%2,%3}, {%4,%5,%6,%7}, {%8,%9}, {%0,%1,%2,%3};"
        : "+f"(d[0]),"+f"(d[1]),"+f"(d[2]),"+f"(d[3])
        : "r"(a[0]),"r"(a[1]),"r"(a[2]),"r"(a[3]),"r"(b[0]),"r"(b[1]));
}
__device__ __forceinline__ void split2(float f, f16&h, f16&l){
    h=__float2half_rn(f); l=__float2half_rn(f-__half2float(h));
}
#define CP16(dst,src) asm volatile("cp.async.cg.shared.global [%0], [%1], 16;"::"r"(dst),"l"(src))
#define CP_COMMIT() asm volatile("cp.async.commit_group;":::"memory")
#define CP_WAIT0() asm volatile("cp.async.wait_group 0;":::"memory")
#define CP_WAIT1() asm volatile("cp.async.wait_group 1;":::"memory")

// ---------- scratch ----------
__device__ float g_pe[SEQ*DMODEL];
__device__ float g_x[MTOK*DMODEL];
__device__ float g_tmp[MTOK*DMODEL];
__device__ float g_sumr[BH*SEQ];
__device__ float g_sc[(size_t)BH*SEQ*SEQ];
__device__ float g_bqkv[NLAYER*1536];
__device__ f16 g_srch[MTOK*DIN], g_srcl[MTOK*DIN];
__device__ f16 g_xh[MTOK*DMODEL], g_xl[MTOK*DMODEL];
__device__ f16 g_qh[MTOK*DMODEL], g_ql[MTOK*DMODEL];
__device__ f16 g_kh[MTOK*DMODEL];
__device__ f16 g_vth[BH*DHEAD*SEQ];
__device__ f16 g_ch[MTOK*DMODEL], g_cl[MTOK*DMODEL];
__device__ f16 g_fh[MTOK*DFF], g_fl[MTOK*DFF];
__device__ f16 g_ph[(size_t)BH*SEQ*SEQ], g_pl[(size_t)BH*SEQ*SEQ];
// weights: hi only (B side of every GEMM)
__device__ f16 g_fw1h[DFF*DIN];
__device__ f16 g_fw2h[DMODEL*DFF];
__device__ f16 g_wqkvh[NLAYER*1536*DMODEL];
__device__ f16 g_woh[NLAYER*DMODEL*DMODEL];
__device__ f16 g_f1h[NLAYER*DFF*DMODEL];
__device__ f16 g_f2h[NLAYER*DMODEL*DFF];

// ---------- weight transpose (hi only) ----------
__device__ __forceinline__ void do_tsplit(const float* __restrict__ W, f16* __restrict__ Oh,
                                          int K, int N, int z, int bx, int by, size_t lstride){
    __shared__ float t[32][33];
    const float* w=W+(size_t)z*K*N;
    f16* oh=Oh+(size_t)z*lstride;
    int n0=bx*32, k0=by*32, tx=threadIdx.x, ty=threadIdx.y;
#pragma unroll
    for(int i=0;i<32;i+=8) t[ty+i][tx]=w[(size_t)(k0+ty+i)*N+n0+tx];
    __syncthreads();
#pragma unroll
    for(int i=0;i<32;i+=8)
        oh[(size_t)(n0+ty+i)*K+k0+tx]=__float2half_rn(t[tx][ty+i]);
}
#define QKVSTRIDE ((size_t)1536*DMODEL)
__global__ void tsplit_all(const float* fin_w1, const float* fin_w2,
    const float* wq, const float* wk, const float* wv, const float* wo,
    const float* ffw1, const float* ffw2,
    f16* fw1h, f16* fw2h, f16* wqkvh, f16* woh, f16* f1h, f16* f2h){
    int bid=blockIdx.x;
    if(bid<128){ int i=bid; do_tsplit(fin_w1,fw1h,DIN,DFF,0,i%64,i/64,0); return; } bid-=128;
    if(bid<1024){ int i=bid; do_tsplit(fin_w2,fw2h,DFF,DMODEL,0,i%16,i/16,0); return; } bid-=1024;
    if(bid<1536){ int i=bid; do_tsplit(wq,wqkvh,        DMODEL,DMODEL,i/256,(i%256)%16,(i%256)/16,QKVSTRIDE); return; } bid-=1536;
    if(bid<1536){ int i=bid; do_tsplit(wk,wqkvh+262144, DMODEL,DMODEL,i/256,(i%256)%16,(i%256)/16,QKVSTRIDE); return; } bid-=1536;
    if(bid<1536){ int i=bid; do_tsplit(wv,wqkvh+524288, DMODEL,DMODEL,i/256,(i%256)%16,(i%256)/16,QKVSTRIDE); return; } bid-=1536;
    if(bid<1536){ int i=bid; do_tsplit(wo,woh,DMODEL,DMODEL,i/256,(i%256)%16,(i%256)/16,(size_t)DMODEL*DMODEL); return; } bid-=1536;
    if(bid<6144){ int i=bid; do_tsplit(ffw1,f1h,DMODEL,DFF,i/1024,(i%1024)%64,(i%1024)/64,(size_t)DMODEL*DFF); return; } bid-=6144;
    { int i=bid; do_tsplit(ffw2,f2h,DFF,DMODEL,i/1024,(i%1024)%16,(i%1024)/16,(size_t)DMODEL*DFF); }
}
#define TSPLIT_BLOCKS (128+1024+4*1536+6144+6144)

#define SRCBLK ((MTOK*DIN+255)/256)
__global__ void prep_misc(float* __restrict__ pe, const float* __restrict__ src,
                          f16* __restrict__ sh, f16* __restrict__ sl,
                          const float* __restrict__ bq, const float* __restrict__ bk,
                          const float* __restrict__ bv, float* __restrict__ bqkv){
    int bid=blockIdx.x, t=threadIdx.x;
    if(bid<SEQ){
        float dv=expf(-(float)(2*t)*(logf(10000.0f)/(float)DMODEL));
        float a=(float)bid*dv;
        pe[bid*DMODEL+2*t]=sinf(a); pe[bid*DMODEL+2*t+1]=cosf(a);
    } else if(bid<SEQ+SRCBLK){
        int i=(bid-SEQ)*256+t;
        if(i<MTOK*DIN){ f16 h,l; split2(src[i],h,l); sh[i]=h; sl[i]=l; }
    } else {
        int i=(bid-SEQ-SRCBLK)*256+t;
        if(i<NLAYER*1536){
            int l=i/1536, r=i%1536;
            float v = r<512 ? bq[l*512+r] : (r<1024 ? bk[l*512+r-512] : bv[l*512+r-1024]);
            bqkv[i]=v;
        }
    }
}
#define PREP_BLOCKS (SEQ + SRCBLK + (NLAYER*1536+255)/256)

// ---------- cp.async loader: nrows x 64 f16 into TROW-stride smem ----------
__device__ __forceinline__ void load_cp(uint32_t dst, const f16* __restrict__ src,
                                        int row0, int k0, int ld, int nrows){
    for(int idx=threadIdx.x; idx<nrows*8; idx+=256){
        int r=idx>>3, c8=idx&7;
        CP16(dst + r*TROW + c8*16, src + (size_t)(row0+r)*ld + k0 + c8*8);
    }
}

// one K-64 chunk of fp16 2-term mma (A hi/lo, B hi), term-major
template<int MI,int NI>
__device__ __forceinline__ void mma_chunk(uint32_t sa, uint32_t sal, uint32_t sb,
                                          float (*acc)[4], int lane, int wm, int wn){
    int ar=(lane&7)+((lane>>3)&1)*8, abit=((lane>>4)&1)*8;
    int br=(lane&7)+((lane>>4)&1)*8, bbit=((lane>>3)&1)*8;
#pragma unroll
    for(int kk=0;kk<4;kk++){
        uint32_t ah[MI][4], al[MI][4], bh[NI][2];
        int ac=kk*16+abit, bc=kk*16+bbit;
#pragma unroll
        for(int mi=0;mi<MI;mi++){
            uint32_t off=(uint32_t)((wm+mi*16+ar)*TROW + ac*2);
            ldsm4(ah[mi], sa+off); ldsm4(al[mi], sal+off);
        }
#pragma unroll
        for(int nj=0;nj<NI/2;nj++){
            uint32_t off=(uint32_t)((wn+nj*16+br)*TROW + bc*2);
            uint32_t r[4];
            ldsm4(r, sb+off);
            bh[nj*2][0]=r[0]; bh[nj*2][1]=r[1]; bh[nj*2+1][0]=r[2]; bh[nj*2+1][1]=r[3];
        }
#pragma unroll
        for(int mi=0;mi<MI;mi++)
#pragma unroll
            for(int ni=0;ni<NI;ni++) mma16816(acc[mi*NI+ni], ah[mi], bh[ni]);
#pragma unroll
        for(int mi=0;mi<MI;mi++)
#pragma unroll
            for(int ni=0;ni<NI;ni++) mma16816(acc[mi*NI+ni], al[mi], bh[ni]);
    }
}

// ---------- GEMM: tile 64x128, K-chunk 64, 2-stage ----------
#define GASZ (64*TROW)        // 9216
#define GBSZ (128*TROW)       // 18432
#define GSTG (2*GASZ+GBSZ)    // 36864
#define GSMEM (2*GSTG)        // 73728
// epi: 1 bias,relu->hi/lo | 3 bias->f32 | 4 bias,*alpha,+pe->f32+hi/lo | 5 fused QKV
__global__ __launch_bounds__(256,2)
void gemm_f16(const f16* __restrict__ Ah, const f16* __restrict__ Al, int lda,
              const f16* __restrict__ Bh, int K,
              const float* __restrict__ bias, int epi,
              float* __restrict__ of, f16* __restrict__ oh, f16* __restrict__ ol,
              f16* __restrict__ kh, f16* __restrict__ vh,
              int ldc, float alpha, const float* __restrict__ pe){
    extern __shared__ char smem[];
    uint32_t sb0=smem_u32(smem);
    int tid=threadIdx.x, wid=tid>>5, lane=tid&31;
    int row0=blockIdx.y*64, col0=blockIdx.x*128;
    int wm=(wid>>2)*32, wn=(wid&3)*32;
    float acc[8][4];
#pragma unroll
    for(int i=0;i<8;i++){ acc[i][0]=0;acc[i][1]=0;acc[i][2]=0;acc[i][3]=0; }
    int NC=K/64;
    {
        uint32_t s=sb0;
        load_cp(s,        Ah,row0,0,lda,64);
        load_cp(s+GASZ,   Al,row0,0,lda,64);
        load_cp(s+2*GASZ, Bh,col0,0,K,128);
        CP_COMMIT();
    }
    for(int kc=0;kc<NC;kc++){
        if(kc+1<NC){
            uint32_t s=sb0+((kc+1)&1)*GSTG;
            int k0=(kc+1)*64;
            load_cp(s,        Ah,row0,k0,lda,64);
            load_cp(s+GASZ,   Al,row0,k0,lda,64);
            load_cp(s+2*GASZ, Bh,col0,k0,K,128);
            CP_COMMIT();
            CP_WAIT1();
        } else CP_WAIT0();
        __syncthreads();
        uint32_t s=sb0+(kc&1)*GSTG;
        mma_chunk<2,4>(s,s+GASZ,s+2*GASZ,acc,lane,wm,wn);
        __syncthreads();
    }
    int gid=lane>>2, tig=lane&3;
#pragma unroll
    for(int mi=0;mi<2;mi++)
#pragma unroll
    for(int ni=0;ni<4;ni++){
        float* d=acc[mi*4+ni];
#pragma unroll
        for(int hf=0;hf<2;hf++){
            int r=row0+wm+mi*16+gid+hf*8;
            int c=col0+wn+ni*8+tig*2;
            float v0=d[hf*2]+__ldg(&bias[c]), v1=d[hf*2+1]+__ldg(&bias[c+1]);
            if(epi==1){ v0=fmaxf(v0,0.f); v1=fmaxf(v1,0.f); }
            if(epi==4){
                const float* per=pe+(size_t)(r&(SEQ-1))*DMODEL+c;
                v0=v0*alpha+per[0]; v1=v1*alpha+per[1];
            }
            if(epi==3||epi==4) *(float2*)(of+(size_t)r*ldc+c)=make_float2(v0,v1);
            if(epi==1||epi==4){
                f16 h0,l0,h1,l1; split2(v0,h0,l0); split2(v1,h1,l1);
                __half2 H{h0,h1}, L{l0,l1};
                *(__half2*)(oh+(size_t)r*ldc+c)=H;
                *(__half2*)(ol+(size_t)r*ldc+c)=L;
            }
            if(epi==5){
                if(c<512){
                    size_t off=(size_t)r*DMODEL+c;
                    f16 h0,l0,h1,l1; split2(v0,h0,l0); split2(v1,h1,l1);
                    __half2 H{h0,h1}, L{l0,l1};
                    *(__half2*)(oh+off)=H; *(__half2*)(ol+off)=L;
                } else if(c<1024){
                    size_t off=(size_t)r*DMODEL+(c-512);
                    __half2 H{__float2half_rn(v0),__float2half_rn(v1)};
                    *(__half2*)(kh+off)=H;
                } else {
                    int b=r>>9, s=r&(SEQ-1);
#pragma unroll
                    for(int u=0;u<2;u++){
                        int n=(c&511)+u; float v=u?v1:v0;
                        size_t off=((size_t)(b*NHEAD+(n>>6))*DHEAD+(n&63))*SEQ+s;
                        vh[off]=__float2half_rn(v);
                    }
                }
            }
        }
    }
}

// ---------- QK^T -> f32 scores. Q hi/lo, K hi. grid(4,4,BH) ----------
#define QASZ (128*TROW)       // 18432
#define QSMEM (3*QASZ)        // 55296
__global__ __launch_bounds__(256,2)
void qk_kernel(const f16* __restrict__ qh, const f16* __restrict__ ql,
               const f16* __restrict__ kh, float* __restrict__ sc, float scale){
    extern __shared__ char smem[];
    uint32_t sb0=smem_u32(smem);
    int tid=threadIdx.x, wid=tid>>5, lane=tid&31;
    int z=blockIdx.z, b=z>>3, h=z&7;
    int row0=blockIdx.y*128, col0=blockIdx.x*128, k0=h*DHEAD;
    int wm=(wid>>2)*64, wn=(wid&3)*32;
    float acc[16][4];
#pragma unroll
    for(int i=0;i<16;i++){ acc[i][0]=0;acc[i][1]=0;acc[i][2]=0;acc[i][3]=0; }
    load_cp(sb0,        qh,b*SEQ+row0,k0,DMODEL,128);
    load_cp(sb0+QASZ,   ql,b*SEQ+row0,k0,DMODEL,128);
    load_cp(sb0+2*QASZ, kh,b*SEQ+col0,k0,DMODEL,128);
    CP_COMMIT(); CP_WAIT0();
    __syncthreads();
    mma_chunk<4,4>(sb0,sb0+QASZ,sb0+2*QASZ,acc,lane,wm,wn);
    int gid=lane>>2, tig=lane&3;
    float* eb=sc+(size_t)z*SEQ*SEQ;
#pragma unroll
    for(int mi=0;mi<4;mi++)
#pragma unroll
    for(int ni=0;ni<4;ni++){
        float* d=acc[mi*4+ni];
#pragma unroll
        for(int hf=0;hf<2;hf++){
            int r=row0+wm+mi*16+gid+hf*8, c=col0+wn+ni*8+tig*2;
            *(float2*)(eb+(size_t)r*SEQ+c)=make_float2(d[hf*2]*scale,d[hf*2+1]*scale);
        }
    }
}

// ---------- softmax -> unnormalized exp hi/lo + 1/sum ----------
__global__ __launch_bounds__(128)
void softmax_kernel(const float* __restrict__ sc, f16* __restrict__ ph, f16* __restrict__ pl,
                    float* __restrict__ sumr){
    __shared__ float red[128];
    int row=blockIdx.x, t=threadIdx.x;
    const float4* p=(const float4*)(sc+(size_t)row*SEQ);
    float4 v=p[t];
    float m=fmaxf(fmaxf(v.x,v.y),fmaxf(v.z,v.w));
    red[t]=m; __syncthreads();
    for(int s=64;s>0;s>>=1){ if(t<s) red[t]=fmaxf(red[t],red[t+s]); __syncthreads(); }
    m=red[0]; __syncthreads();
    float e0=__expf(v.x-m), e1=__expf(v.y-m), e2=__expf(v.z-m), e3=__expf(v.w-m);
    red[t]=e0+e1+e2+e3; __syncthreads();
    for(int s=64;s>0;s>>=1){ if(t<s) red[t]+=red[t+s]; __syncthreads(); }
    if(t==0) sumr[row]=1.0f/red[0];
    size_t off=(size_t)row*SEQ+t*4;
    f16 h0,l0,h1,l1,h2,l2,h3,l3;
    split2(e0,h0,l0); split2(e1,h1,l1); split2(e2,h2,l2); split2(e3,h3,l3);
    __half2 H0{h0,h1},H1{h2,h3},L0{l0,l1},L1{l2,l3};
    *(__half2*)(ph+off)=H0; *(__half2*)(ph+off+2)=H1;
    *(__half2*)(pl+off)=L0; *(__half2*)(pl+off+2)=L1;
}

// ---------- attn @ V: P hi/lo, V hi. K-chunk 64, 2-stage. grid(4,BH) ----------
#define AASZ (128*TROW)       // 18432
#define ABSZ (64*TROW)        // 9216
#define ASTG (2*AASZ+ABSZ)    // 46080
#define ASMEM (2*ASTG)        // 92160
__global__ __launch_bounds__(256,2)
void av_f16(const f16* __restrict__ ph, const f16* __restrict__ pl,
            const f16* __restrict__ vth, const float* __restrict__ sumr,
            f16* __restrict__ ch, f16* __restrict__ cl){
    extern __shared__ char smem[];
    uint32_t sb0=smem_u32(smem);
    int tid=threadIdx.x, wid=tid>>5, lane=tid&31;
    int z=blockIdx.y, b=z>>3, h=z&7;
    int row0=blockIdx.x*128;
    int wm=(wid>>2)*64, wn=(wid&3)*16;
    float acc[8][4];
#pragma unroll
    for(int i=0;i<8;i++){ acc[i][0]=0;acc[i][1]=0;acc[i][2]=0;acc[i][3]=0; }
    const f16* pbh=ph+(size_t)z*SEQ*SEQ;
    const f16* pbl=pl+(size_t)z*SEQ*SEQ;
    {
        uint32_t s=sb0;
        load_cp(s,        pbh,row0,0,SEQ,128);
        load_cp(s+AASZ,   pbl,row0,0,SEQ,128);
        load_cp(s+2*AASZ, vth,z*DHEAD,0,SEQ,64);
        CP_COMMIT();
    }
    for(int kc=0;kc<8;kc++){
        if(kc+1<8){
            uint32_t s=sb0+((kc+1)&1)*ASTG;
            int k0=(kc+1)*64;
            load_cp(s,        pbh,row0,k0,SEQ,128);
            load_cp(s+AASZ,   pbl,row0,k0,SEQ,128);
            load_cp(s+2*AASZ, vth,z*DHEAD,k0,SEQ,64);
            CP_COMMIT();
            CP_WAIT1();
        } else CP_WAIT0();
        __syncthreads();
        uint32_t s=sb0+(kc&1)*ASTG;
        mma_chunk<4,2>(s,s+AASZ,s+2*AASZ,acc,lane,wm,wn);
        __syncthreads();
    }
    int gid=lane>>2, tig=lane&3;
#pragma unroll
    for(int mi=0;mi<4;mi++)
#pragma unroll
    for(int ni=0;ni<2;ni++){
        float* d=acc[mi*2+ni];
#pragma unroll
        for(int hf=0;hf<2;hf++){
            int rl=row0+wm+mi*16+gid+hf*8;
            float inv=sumr[(size_t)z*SEQ+rl];
            int token=b*SEQ+rl, c=wn+ni*8+tig*2;
            float v0=d[hf*2]*inv, v1=d[hf*2+1]*inv;
            f16 h0,l0,h1,l1; split2(v0,h0,l0); split2(v1,h1,l1);
            __half2 H{h0,h1}, L{l0,l1};
            size_t off=(size_t)token*DMODEL+h*DHEAD+c;
            *(__half2*)(ch+off)=H; *(__half2*)(cl+off)=L;
        }
    }
}

// ---------- residual + LN -> f32 + hi/lo ----------
__global__ __launch_bounds__(128)
void ln_kernel(const float* __restrict__ x, const float* __restrict__ res,
               const float* __restrict__ gs, const float* __restrict__ gb,
               float* __restrict__ out, f16* __restrict__ oh, f16* __restrict__ ol){
    __shared__ float red[128];
    int row=blockIdx.x, t=threadIdx.x;
    float4 a=*(const float4*)&x[(size_t)row*DMODEL+t*4];
    float4 r=*(const float4*)&res[(size_t)row*DMODEL+t*4];
    float y0=a.x+r.x, y1=a.y+r.y, y2=a.z+r.z, y3=a.w+r.w;
    red[t]=y0+y1+y2+y3; __syncthreads();
    for(int s=64;s>0;s>>=1){ if(t<s) red[t]+=red[t+s]; __syncthreads(); }
    float mu=red[0]*(1.0f/DMODEL); __syncthreads();
    float d0=y0-mu,d1=y1-mu,d2=y2-mu,d3=y3-mu;
    red[t]=d0*d0+d1*d1+d2*d2+d3*d3; __syncthreads();
    for(int s=64;s>0;s>>=1){ if(t<s) red[t]+=red[t+s]; __syncthreads(); }
    float k=rsqrtf(red[0]*(1.0f/DMODEL)+1e-5f);
    float4 sv=*(const float4*)&gs[t*4], bv=*(const float4*)&gb[t*4];
    float o0=d0*k*sv.x+bv.x, o1=d1*k*sv.y+bv.y, o2=d2*k*sv.z+bv.z, o3=d3*k*sv.w+bv.w;
    *(float4*)&out[(size_t)row*DMODEL+t*4]=make_float4(o0,o1,o2,o3);
    size_t off=(size_t)row*DMODEL+t*4;
    f16 h0,l0,h1,l1,h2,l2,h3,l3;
    split2(o0,h0,l0); split2(o1,h1,l1); split2(o2,h2,l2); split2(o3,h3,l3);
    __half2 H0{h0,h1},H1{h2,h3},L0{l0,l1},L1{l2,l3};
    *(__half2*)(oh+off)=H0; *(__half2*)(oh+off+2)=H1;
    *(__half2*)(ol+off)=L0; *(__half2*)(ol+off+2)=L1;
}

// ---------- host ----------
#define GETP(sym,p,T) do{ void* _t; cudaGetSymbolAddress(&_t,sym); p=(T*)_t; }while(0)

extern "C" void kernel_launch(void* const* d_in, const int* in_sizes, int n_in,
                              void* d_out, int out_size){
    const float* source=(const float*)d_in[0];
    const float* fin_w1=(const float*)d_in[2];
    const float* fin_b1=(const float*)d_in[3];
    const float* fin_w2=(const float*)d_in[4];
    const float* fin_b2=(const float*)d_in[5];
    const float* wq=(const float*)d_in[6];  const float* bq=(const float*)d_in[7];
    const float* wk=(const float*)d_in[8];  const float* bk=(const float*)d_in[9];
    const float* wv=(const float*)d_in[10]; const float* bvv=(const float*)d_in[11];
    const float* wo=(const float*)d_in[12]; const float* bo=(const float*)d_in[13];
    const float* n1s=(const float*)d_in[14]; const float* n1b=(const float*)d_in[15];
    const float* ffw1=(const float*)d_in[16]; const float* ffb1=(const float*)d_in[17];
    const float* ffw2=(const float*)d_in[18]; const float* ffb2=(const float*)d_in[19];
    const float* n2s=(const float*)d_in[20]; const float* n2b=(const float*)d_in[21];
    float* out=(float*)d_out;

    float *ppe,*px,*ptmp,*psumr,*psc,*pbqkv;
    GETP(g_pe,ppe,float); GETP(g_x,px,float); GETP(g_tmp,ptmp,float);
    GETP(g_sumr,psumr,float); GETP(g_sc,psc,float); GETP(g_bqkv,pbqkv,float);
    f16 *srch,*srcl,*xh,*xl,*qh,*ql,*kh,*vth,*chh,*cll,*fhh,*fll,*phh,*pll;
    GETP(g_srch,srch,f16); GETP(g_srcl,srcl,f16);
    GETP(g_xh,xh,f16); GETP(g_xl,xl,f16);
    GETP(g_qh,qh,f16); GETP(g_ql,ql,f16); GETP(g_kh,kh,f16);
    GETP(g_vth,vth,f16);
    GETP(g_ch,chh,f16); GETP(g_cl,cll,f16);
    GETP(g_fh,fhh,f16); GETP(g_fl,fll,f16);
    GETP(g_ph,phh,f16); GETP(g_pl,pll,f16);
    f16 *fw1h,*fw2h,*wqkvh,*woh,*f1h,*f2h;
    GETP(g_fw1h,fw1h,f16); GETP(g_fw2h,fw2h,f16);
    GETP(g_wqkvh,wqkvh,f16); GETP(g_woh,woh,f16);
    GETP(g_f1h,f1h,f16); GETP(g_f2h,f2h,f16);

    cudaFuncSetAttribute(gemm_f16,  cudaFuncAttributeMaxDynamicSharedMemorySize, GSMEM);
    cudaFuncSetAttribute(qk_kernel, cudaFuncAttributeMaxDynamicSharedMemorySize, QSMEM);
    cudaFuncSetAttribute(av_f16,    cudaFuncAttributeMaxDynamicSharedMemorySize, ASMEM);

    const float sqrtd=22.627416998f, scale=0.044194173824f;

    tsplit_all<<<TSPLIT_BLOCKS, dim3(32,8)>>>(fin_w1,fin_w2,wq,wk,wv,wo,ffw1,ffw2,
        fw1h,fw2h,wqkvh,woh,f1h,f2h);
    prep_misc<<<PREP_BLOCKS,256>>>(ppe,source,srch,srcl,bq,bk,bvv,pbqkv);

    // input FFN
    gemm_f16<<<dim3(16,64),256,GSMEM>>>(srch,srcl,DIN,fw1h,DIN,fin_b1,1,
        nullptr,fhh,fll,nullptr,nullptr,DFF,0.f,nullptr);
    gemm_f16<<<dim3(4,64),256,GSMEM>>>(fhh,fll,DFF,fw2h,DFF,fin_b2,4,
        px,xh,xl,nullptr,nullptr,DMODEL,sqrtd,ppe);

    for(int l=0;l<NLAYER;l++){
        size_t w5=(size_t)l*DMODEL*DMODEL;
        size_t wqkv=(size_t)l*1536*DMODEL;
        size_t wf1=(size_t)l*DFF*DMODEL, wf2=(size_t)l*DMODEL*DFF;

        gemm_f16<<<dim3(12,64),256,GSMEM>>>(xh,xl,DMODEL,wqkvh+wqkv,DMODEL,
            pbqkv+l*1536,5,nullptr,qh,ql,kh,vth,DMODEL,0.f,nullptr);

        qk_kernel<<<dim3(4,4,BH),256,QSMEM>>>(qh,ql,kh,psc,scale);
        softmax_kernel<<<BH*SEQ,128>>>(psc,phh,pll,psumr);
        av_f16<<<dim3(4,BH),256,ASMEM>>>(phh,pll,vth,psumr,chh,cll);

        gemm_f16<<<dim3(4,64),256,GSMEM>>>(chh,cll,DMODEL,woh+w5,DMODEL,bo+l*DMODEL,3,
            ptmp,nullptr,nullptr,nullptr,nullptr,DMODEL,0.f,nullptr);
        ln_kernel<<<MTOK,128>>>(px,ptmp,n1s+l*DMODEL,n1b+l*DMODEL,px,xh,xl);

        gemm_f16<<<dim3(16,64),256,GSMEM>>>(xh,xl,DMODEL,f1h+wf1,DMODEL,ffb1+l*DFF,1,
            nullptr,fhh,fll,nullptr,nullptr,DFF,0.f,nullptr);
        gemm_f16<<<dim3(4,64),256,GSMEM>>>(fhh,fll,DFF,f2h+wf2,DFF,ffb2+l*DMODEL,3,
            ptmp,nullptr,nullptr,nullptr,nullptr,DMODEL,0.f,nullptr);

        float* lnout=(l==NLAYER-1)?out:px;
        ln_kernel<<<MTOK,128>>>(px,ptmp,n2s+l*DMODEL,n2b+l*DMODEL,lnout,xh,xl);
    }
}

// round 12
// speedup vs baseline: 1.9008x; 1.4005x over previous
#include <cuda_runtime.h>
#include <cuda_fp16.h>
#include <cstdint>
#include <math.h>

#define BATCH 8
#define SEQ 512
#define DMODEL 512
#define NHEAD 8
#define DHEAD 64
#define DFF 2048
#define NLAYER 6
#define DIN 64
#define MTOK (BATCH*SEQ)
#define BH (BATCH*NHEAD)
typedef __half f16;

#define TROW 144   // 72 f16/row, conflict-free ldmatrix

__device__ __forceinline__ uint32_t smem_u32(const void* p){
    uint32_t a; asm("{ .reg .u64 t; cvta.to.shared.u64 t, %1; cvt.u32.u64 %0, t; }":"=r"(a):"l"(p)); return a;
}
__device__ __forceinline__ void ldsm4(uint32_t* r, uint32_t a){
    asm volatile("ldmatrix.sync.aligned.m8n8.x4.shared.b16 {%0,%1,%2,%3}, [%4];"
        : "=r"(r[0]),"=r"(r[1]),"=r"(r[2]),"=r"(r[3]) : "r"(a));
}
__device__ __forceinline__ void mma16816(float* d, const uint32_t* a, const uint32_t* b){
    asm volatile("mma.sync.aligned.m16n8k16.row.col.f32.f16.f16.f32 "
        "{%0,%1,%2,%3}, {%4,%5,%6,%7}, {%8,%9}, {%0,%1,%2,%3};"
        : "+f"(d[0]),"+f"(d[1]),"+f"(d[2]),"+f"(d[3])
        : "r"(a[0]),"r"(a[1]),"r"(a[2]),"r"(a[3]),"r"(b[0]),"r"(b[1]));
}
#define CP16(dst,src) asm volatile("cp.async.cg.shared.global [%0], [%1], 16;"::"r"(dst),"l"(src))
#define CP_COMMIT() asm volatile("cp.async.commit_group;":::"memory")
#define CP_WAIT0() asm volatile("cp.async.wait_group 0;":::"memory")
#define CP_WAIT1() asm volatile("cp.async.wait_group 1;":::"memory")

// ---------- scratch ----------
__device__ float g_pe[SEQ*DMODEL];
__device__ float g_x[MTOK*DMODEL];
__device__ float g_tmp[MTOK*DMODEL];
__device__ float g_sumr[BH*SEQ];
__device__ float g_sc[(size_t)BH*SEQ*SEQ];
__device__ float g_bqkv[NLAYER*1536];
__device__ f16 g_srch[MTOK*DIN];
__device__ f16 g_xh[MTOK*DMODEL];
__device__ f16 g_qh[MTOK*DMODEL];
__device__ f16 g_kh[MTOK*DMODEL];
__device__ f16 g_vth[BH*DHEAD*SEQ];
__device__ f16 g_ch[MTOK*DMODEL];
__device__ f16 g_fh[MTOK*DFF];
__device__ f16 g_ph[(size_t)BH*SEQ*SEQ];
__device__ f16 g_fw1h[DFF*DIN];
__device__ f16 g_fw2h[DMODEL*DFF];
__device__ f16 g_wqkvh[NLAYER*1536*DMODEL];
__device__ f16 g_woh[NLAYER*DMODEL*DMODEL];
__device__ f16 g_f1h[NLAYER*DFF*DMODEL];
__device__ f16 g_f2h[NLAYER*DMODEL*DFF];

// ---------- weight transpose (hi only) ----------
__device__ __forceinline__ void do_tsplit(const float* __restrict__ W, f16* __restrict__ Oh,
                                          int K, int N, int z, int bx, int by, size_t lstride){
    __shared__ float t[32][33];
    const float* w=W+(size_t)z*K*N;
    f16* oh=Oh+(size_t)z*lstride;
    int n0=bx*32, k0=by*32, tx=threadIdx.x, ty=threadIdx.y;
#pragma unroll
    for(int i=0;i<32;i+=8) t[ty+i][tx]=w[(size_t)(k0+ty+i)*N+n0+tx];
    __syncthreads();
#pragma unroll
    for(int i=0;i<32;i+=8)
        oh[(size_t)(n0+ty+i)*K+k0+tx]=__float2half_rn(t[tx][ty+i]);
}
#define QKVSTRIDE ((size_t)1536*DMODEL)
__global__ void tsplit_all(const float* fin_w1, const float* fin_w2,
    const float* wq, const float* wk, const float* wv, const float* wo,
    const float* ffw1, const float* ffw2,
    f16* fw1h, f16* fw2h, f16* wqkvh, f16* woh, f16* f1h, f16* f2h){
    int bid=blockIdx.x;
    if(bid<128){ int i=bid; do_tsplit(fin_w1,fw1h,DIN,DFF,0,i%64,i/64,0); return; } bid-=128;
    if(bid<1024){ int i=bid; do_tsplit(fin_w2,fw2h,DFF,DMODEL,0,i%16,i/16,0); return; } bid-=1024;
    if(bid<1536){ int i=bid; do_tsplit(wq,wqkvh,        DMODEL,DMODEL,i/256,(i%256)%16,(i%256)/16,QKVSTRIDE); return; } bid-=1536;
    if(bid<1536){ int i=bid; do_tsplit(wk,wqkvh+262144, DMODEL,DMODEL,i/256,(i%256)%16,(i%256)/16,QKVSTRIDE); return; } bid-=1536;
    if(bid<1536){ int i=bid; do_tsplit(wv,wqkvh+524288, DMODEL,DMODEL,i/256,(i%256)%16,(i%256)/16,QKVSTRIDE); return; } bid-=1536;
    if(bid<1536){ int i=bid; do_tsplit(wo,woh,DMODEL,DMODEL,i/256,(i%256)%16,(i%256)/16,(size_t)DMODEL*DMODEL); return; } bid-=1536;
    if(bid<6144){ int i=bid; do_tsplit(ffw1,f1h,DMODEL,DFF,i/1024,(i%1024)%64,(i%1024)/64,(size_t)DMODEL*DFF); return; } bid-=6144;
    { int i=bid; do_tsplit(ffw2,f2h,DFF,DMODEL,i/1024,(i%1024)%16,(i%1024)/16,(size_t)DMODEL*DFF); }
}
#define TSPLIT_BLOCKS (128+1024+4*1536+6144+6144)

#define SRCBLK ((MTOK*DIN+255)/256)
__global__ void prep_misc(float* __restrict__ pe, const float* __restrict__ src,
                          f16* __restrict__ sh,
                          const float* __restrict__ bq, const float* __restrict__ bk,
                          const float* __restrict__ bv, float* __restrict__ bqkv){
    int bid=blockIdx.x, t=threadIdx.x;
    if(bid<SEQ){
        float dv=expf(-(float)(2*t)*(logf(10000.0f)/(float)DMODEL));
        float a=(float)bid*dv;
        pe[bid*DMODEL+2*t]=sinf(a); pe[bid*DMODEL+2*t+1]=cosf(a);
    } else if(bid<SEQ+SRCBLK){
        int i=(bid-SEQ)*256+t;
        if(i<MTOK*DIN) sh[i]=__float2half_rn(src[i]);
    } else {
        int i=(bid-SEQ-SRCBLK)*256+t;
        if(i<NLAYER*1536){
            int l=i/1536, r=i%1536;
            float v = r<512 ? bq[l*512+r] : (r<1024 ? bk[l*512+r-512] : bv[l*512+r-1024]);
            bqkv[i]=v;
        }
    }
}
#define PREP_BLOCKS (SEQ + SRCBLK + (NLAYER*1536+255)/256)

// ---------- cp.async loader: nrows x 64 f16 into TROW-stride smem ----------
__device__ __forceinline__ void load_cp(uint32_t dst, const f16* __restrict__ src,
                                        int row0, int k0, int ld, int nrows){
    for(int idx=threadIdx.x; idx<nrows*8; idx+=256){
        int r=idx>>3, c8=idx&7;
        CP16(dst + r*TROW + c8*16, src + (size_t)(row0+r)*ld + k0 + c8*8);
    }
}

// one K-64 chunk of single-term fp16 mma
template<int MI,int NI>
__device__ __forceinline__ void mma_chunk(uint32_t sa, uint32_t sb,
                                          float (*acc)[4], int lane, int wm, int wn){
    int ar=(lane&7)+((lane>>3)&1)*8, abit=((lane>>4)&1)*8;
    int br=(lane&7)+((lane>>4)&1)*8, bbit=((lane>>3)&1)*8;
#pragma unroll
    for(int kk=0;kk<4;kk++){
        uint32_t ah[MI][4], bh[NI][2];
        int ac=kk*16+abit, bc=kk*16+bbit;
#pragma unroll
        for(int mi=0;mi<MI;mi++){
            uint32_t off=(uint32_t)((wm+mi*16+ar)*TROW + ac*2);
            ldsm4(ah[mi], sa+off);
        }
#pragma unroll
        for(int nj=0;nj<NI/2;nj++){
            uint32_t off=(uint32_t)((wn+nj*16+br)*TROW + bc*2);
            uint32_t r[4];
            ldsm4(r, sb+off);
            bh[nj*2][0]=r[0]; bh[nj*2][1]=r[1]; bh[nj*2+1][0]=r[2]; bh[nj*2+1][1]=r[3];
        }
#pragma unroll
        for(int mi=0;mi<MI;mi++)
#pragma unroll
            for(int ni=0;ni<NI;ni++) mma16816(acc[mi*NI+ni], ah[mi], bh[ni]);
    }
}

// ---------- GEMM: tile 64x128, K-chunk 64, 2-stage ----------
#define GASZ (64*TROW)        // 9216
#define GBSZ (128*TROW)       // 18432
#define GSTG (GASZ+GBSZ)      // 27648
#define GSMEM (2*GSTG)        // 55296
// epi: 1 bias,relu->hi | 3 bias->f32 | 4 bias,*alpha,+pe->f32+hi | 5 fused QKV
__global__ __launch_bounds__(256,2)
void gemm_f16(const f16* __restrict__ Ah, int lda,
              const f16* __restrict__ Bh, int K,
              const float* __restrict__ bias, int epi,
              float* __restrict__ of, f16* __restrict__ oh,
              f16* __restrict__ kh, f16* __restrict__ vh,
              int ldc, float alpha, const float* __restrict__ pe){
    extern __shared__ char smem[];
    uint32_t sb0=smem_u32(smem);
    int tid=threadIdx.x, wid=tid>>5, lane=tid&31;
    int row0=blockIdx.y*64, col0=blockIdx.x*128;
    int wm=(wid>>2)*32, wn=(wid&3)*32;
    float acc[8][4];
#pragma unroll
    for(int i=0;i<8;i++){ acc[i][0]=0;acc[i][1]=0;acc[i][2]=0;acc[i][3]=0; }
    int NC=K/64;
    {
        load_cp(sb0,      Ah,row0,0,lda,64);
        load_cp(sb0+GASZ, Bh,col0,0,K,128);
        CP_COMMIT();
    }
    for(int kc=0;kc<NC;kc++){
        if(kc+1<NC){
            uint32_t s=sb0+((kc+1)&1)*GSTG;
            int k0=(kc+1)*64;
            load_cp(s,      Ah,row0,k0,lda,64);
            load_cp(s+GASZ, Bh,col0,k0,K,128);
            CP_COMMIT();
            CP_WAIT1();
        } else CP_WAIT0();
        __syncthreads();
        uint32_t s=sb0+(kc&1)*GSTG;
        mma_chunk<2,4>(s,s+GASZ,acc,lane,wm,wn);
        __syncthreads();
    }
    int gid=lane>>2, tig=lane&3;
#pragma unroll
    for(int mi=0;mi<2;mi++)
#pragma unroll
    for(int ni=0;ni<4;ni++){
        float* d=acc[mi*4+ni];
#pragma unroll
        for(int hf=0;hf<2;hf++){
            int r=row0+wm+mi*16+gid+hf*8;
            int c=col0+wn+ni*8+tig*2;
            float v0=d[hf*2]+__ldg(&bias[c]), v1=d[hf*2+1]+__ldg(&bias[c+1]);
            if(epi==1){ v0=fmaxf(v0,0.f); v1=fmaxf(v1,0.f); }
            if(epi==4){
                const float* per=pe+(size_t)(r&(SEQ-1))*DMODEL+c;
                v0=v0*alpha+per[0]; v1=v1*alpha+per[1];
            }
            if(epi==3||epi==4) *(float2*)(of+(size_t)r*ldc+c)=make_float2(v0,v1);
            if(epi==1||epi==4){
                __half2 H{__float2half_rn(v0),__float2half_rn(v1)};
                *(__half2*)(oh+(size_t)r*ldc+c)=H;
            }
            if(epi==5){
                __half2 H{__float2half_rn(v0),__float2half_rn(v1)};
                if(c<512){
                    *(__half2*)(oh+(size_t)r*DMODEL+c)=H;
                } else if(c<1024){
                    *(__half2*)(kh+(size_t)r*DMODEL+(c-512))=H;
                } else {
                    int b=r>>9, s=r&(SEQ-1);
#pragma unroll
                    for(int u=0;u<2;u++){
                        int n=(c&511)+u; float v=u?v1:v0;
                        size_t off=((size_t)(b*NHEAD+(n>>6))*DHEAD+(n&63))*SEQ+s;
                        vh[off]=__float2half_rn(v);
                    }
                }
            }
        }
    }
}

// ---------- QK^T -> f32 scores. grid(4,4,BH) ----------
#define QASZ (128*TROW)       // 18432
#define QSMEM (2*QASZ)        // 36864
__global__ __launch_bounds__(256,2)
void qk_kernel(const f16* __restrict__ qh, const f16* __restrict__ kh,
               float* __restrict__ sc, float scale){
    extern __shared__ char smem[];
    uint32_t sb0=smem_u32(smem);
    int tid=threadIdx.x, wid=tid>>5, lane=tid&31;
    int z=blockIdx.z, b=z>>3, h=z&7;
    int row0=blockIdx.y*128, col0=blockIdx.x*128, k0=h*DHEAD;
    int wm=(wid>>2)*64, wn=(wid&3)*32;
    float acc[16][4];
#pragma unroll
    for(int i=0;i<16;i++){ acc[i][0]=0;acc[i][1]=0;acc[i][2]=0;acc[i][3]=0; }
    load_cp(sb0,      qh,b*SEQ+row0,k0,DMODEL,128);
    load_cp(sb0+QASZ, kh,b*SEQ+col0,k0,DMODEL,128);
    CP_COMMIT(); CP_WAIT0();
    __syncthreads();
    mma_chunk<4,4>(sb0,sb0+QASZ,acc,lane,wm,wn);
    int gid=lane>>2, tig=lane&3;
    float* eb=sc+(size_t)z*SEQ*SEQ;
#pragma unroll
    for(int mi=0;mi<4;mi++)
#pragma unroll
    for(int ni=0;ni<4;ni++){
        float* d=acc[mi*4+ni];
#pragma unroll
        for(int hf=0;hf<2;hf++){
            int r=row0+wm+mi*16+gid+hf*8, c=col0+wn+ni*8+tig*2;
            *(float2*)(eb+(size_t)r*SEQ+c)=make_float2(d[hf*2]*scale,d[hf*2+1]*scale);
        }
    }
}

// ---------- softmax -> unnormalized exp hi + 1/sum ----------
__global__ __launch_bounds__(128)
void softmax_kernel(const float* __restrict__ sc, f16* __restrict__ ph,
                    float* __restrict__ sumr){
    __shared__ float red[128];
    int row=blockIdx.x, t=threadIdx.x;
    const float4* p=(const float4*)(sc+(size_t)row*SEQ);
    float4 v=p[t];
    float m=fmaxf(fmaxf(v.x,v.y),fmaxf(v.z,v.w));
    red[t]=m; __syncthreads();
    for(int s=64;s>0;s>>=1){ if(t<s) red[t]=fmaxf(red[t],red[t+s]); __syncthreads(); }
    m=red[0]; __syncthreads();
    float e0=__expf(v.x-m), e1=__expf(v.y-m), e2=__expf(v.z-m), e3=__expf(v.w-m);
    red[t]=e0+e1+e2+e3; __syncthreads();
    for(int s=64;s>0;s>>=1){ if(t<s) red[t]+=red[t+s]; __syncthreads(); }
    if(t==0) sumr[row]=1.0f/red[0];
    size_t off=(size_t)row*SEQ+t*4;
    __half2 H0{__float2half_rn(e0),__float2half_rn(e1)};
    __half2 H1{__float2half_rn(e2),__float2half_rn(e3)};
    *(__half2*)(ph+off)=H0; *(__half2*)(ph+off+2)=H1;
}

// ---------- attn @ V: P hi, V hi. K-chunk 64, 2-stage. grid(4,BH) ----------
#define AASZ (128*TROW)       // 18432
#define ABSZ (64*TROW)        // 9216
#define ASTG (AASZ+ABSZ)      // 27648
#define ASMEM (2*ASTG)        // 55296
__global__ __launch_bounds__(256,2)
void av_f16(const f16* __restrict__ ph, const f16* __restrict__ vth,
            const float* __restrict__ sumr, f16* __restrict__ ch){
    extern __shared__ char smem[];
    uint32_t sb0=smem_u32(smem);
    int tid=threadIdx.x, wid=tid>>5, lane=tid&31;
    int z=blockIdx.y, b=z>>3, h=z&7;
    int row0=blockIdx.x*128;
    int wm=(wid>>2)*64, wn=(wid&3)*16;
    float acc[8][4];
#pragma unroll
    for(int i=0;i<8;i++){ acc[i][0]=0;acc[i][1]=0;acc[i][2]=0;acc[i][3]=0; }
    const f16* pbh=ph+(size_t)z*SEQ*SEQ;
    {
        load_cp(sb0,      pbh,row0,0,SEQ,128);
        load_cp(sb0+AASZ, vth,z*DHEAD,0,SEQ,64);
        CP_COMMIT();
    }
    for(int kc=0;kc<8;kc++){
        if(kc+1<8){
            uint32_t s=sb0+((kc+1)&1)*ASTG;
            int k0=(kc+1)*64;
            load_cp(s,      pbh,row0,k0,SEQ,128);
            load_cp(s+AASZ, vth,z*DHEAD,k0,SEQ,64);
            CP_COMMIT();
            CP_WAIT1();
        } else CP_WAIT0();
        __syncthreads();
        uint32_t s=sb0+(kc&1)*ASTG;
        mma_chunk<4,2>(s,s+AASZ,acc,lane,wm,wn);
        __syncthreads();
    }
    int gid=lane>>2, tig=lane&3;
#pragma unroll
    for(int mi=0;mi<4;mi++)
#pragma unroll
    for(int ni=0;ni<2;ni++){
        float* d=acc[mi*2+ni];
#pragma unroll
        for(int hf=0;hf<2;hf++){
            int rl=row0+wm+mi*16+gid+hf*8;
            float inv=sumr[(size_t)z*SEQ+rl];
            int token=b*SEQ+rl, c=wn+ni*8+tig*2;
            float v0=d[hf*2]*inv, v1=d[hf*2+1]*inv;
            __half2 H{__float2half_rn(v0),__float2half_rn(v1)};
            *(__half2*)(ch+(size_t)token*DMODEL+h*DHEAD+c)=H;
        }
    }
}

// ---------- residual + LN -> f32 + hi ----------
__global__ __launch_bounds__(128)
void ln_kernel(const float* __restrict__ x, const float* __restrict__ res,
               const float* __restrict__ gs, const float* __restrict__ gb,
               float* __restrict__ out, f16* __restrict__ oh){
    __shared__ float red[128];
    int row=blockIdx.x, t=threadIdx.x;
    float4 a=*(const float4*)&x[(size_t)row*DMODEL+t*4];
    float4 r=*(const float4*)&res[(size_t)row*DMODEL+t*4];
    float y0=a.x+r.x, y1=a.y+r.y, y2=a.z+r.z, y3=a.w+r.w;
    red[t]=y0+y1+y2+y3; __syncthreads();
    for(int s=64;s>0;s>>=1){ if(t<s) red[t]+=red[t+s]; __syncthreads(); }
    float mu=red[0]*(1.0f/DMODEL); __syncthreads();
    float d0=y0-mu,d1=y1-mu,d2=y2-mu,d3=y3-mu;
    red[t]=d0*d0+d1*d1+d2*d2+d3*d3; __syncthreads();
    for(int s=64;s>0;s>>=1){ if(t<s) red[t]+=red[t+s]; __syncthreads(); }
    float k=rsqrtf(red[0]*(1.0f/DMODEL)+1e-5f);
    float4 sv=*(const float4*)&gs[t*4], bv=*(const float4*)&gb[t*4];
    float o0=d0*k*sv.x+bv.x, o1=d1*k*sv.y+bv.y, o2=d2*k*sv.z+bv.z, o3=d3*k*sv.w+bv.w;
    *(float4*)&out[(size_t)row*DMODEL+t*4]=make_float4(o0,o1,o2,o3);
    size_t off=(size_t)row*DMODEL+t*4;
    __half2 H0{__float2half_rn(o0),__float2half_rn(o1)};
    __half2 H1{__float2half_rn(o2),__float2half_rn(o3)};
    *(__half2*)(oh+off)=H0; *(__half2*)(oh+off+2)=H1;
}

// ---------- host ----------
#define GETP(sym,p,T) do{ void* _t; cudaGetSymbolAddress(&_t,sym); p=(T*)_t; }while(0)

extern "C" void kernel_launch(void* const* d_in, const int* in_sizes, int n_in,
                              void* d_out, int out_size){
    const float* source=(const float*)d_in[0];
    const float* fin_w1=(const float*)d_in[2];
    const float* fin_b1=(const float*)d_in[3];
    const float* fin_w2=(const float*)d_in[4];
    const float* fin_b2=(const float*)d_in[5];
    const float* wq=(const float*)d_in[6];  const float* bq=(const float*)d_in[7];
    const float* wk=(const float*)d_in[8];  const float* bk=(const float*)d_in[9];
    const float* wv=(const float*)d_in[10]; const float* bvv=(const float*)d_in[11];
    const float* wo=(const float*)d_in[12]; const float* bo=(const float*)d_in[13];
    const float* n1s=(const float*)d_in[14]; const float* n1b=(const float*)d_in[15];
    const float* ffw1=(const float*)d_in[16]; const float* ffb1=(const float*)d_in[17];
    const float* ffw2=(const float*)d_in[18]; const float* ffb2=(const float*)d_in[19];
    const float* n2s=(const float*)d_in[20]; const float* n2b=(const float*)d_in[21];
    float* out=(float*)d_out;

    float *ppe,*px,*ptmp,*psumr,*psc,*pbqkv;
    GETP(g_pe,ppe,float); GETP(g_x,px,float); GETP(g_tmp,ptmp,float);
    GETP(g_sumr,psumr,float); GETP(g_sc,psc,float); GETP(g_bqkv,pbqkv,float);
    f16 *srch,*xh,*qh,*kh,*vth,*chh,*fhh,*phh;
    GETP(g_srch,srch,f16); GETP(g_xh,xh,f16);
    GETP(g_qh,qh,f16); GETP(g_kh,kh,f16); GETP(g_vth,vth,f16);
    GETP(g_ch,chh,f16); GETP(g_fh,fhh,f16); GETP(g_ph,phh,f16);
    f16 *fw1h,*fw2h,*wqkvh,*woh,*f1h,*f2h;
    GETP(g_fw1h,fw1h,f16); GETP(g_fw2h,fw2h,f16);
    GETP(g_wqkvh,wqkvh,f16); GETP(g_woh,woh,f16);
    GETP(g_f1h,f1h,f16); GETP(g_f2h,f2h,f16);

    cudaFuncSetAttribute(gemm_f16,  cudaFuncAttributeMaxDynamicSharedMemorySize, GSMEM);
    cudaFuncSetAttribute(qk_kernel, cudaFuncAttributeMaxDynamicSharedMemorySize, QSMEM);
    cudaFuncSetAttribute(av_f16,    cudaFuncAttributeMaxDynamicSharedMemorySize, ASMEM);

    const float sqrtd=22.627416998f, scale=0.044194173824f;

    tsplit_all<<<TSPLIT_BLOCKS, dim3(32,8)>>>(fin_w1,fin_w2,wq,wk,wv,wo,ffw1,ffw2,
        fw1h,fw2h,wqkvh,woh,f1h,f2h);
    prep_misc<<<PREP_BLOCKS,256>>>(ppe,source,srch,bq,bk,bvv,pbqkv);

    // input FFN
    gemm_f16<<<dim3(16,64),256,GSMEM>>>(srch,DIN,fw1h,DIN,fin_b1,1,
        nullptr,fhh,nullptr,nullptr,DFF,0.f,nullptr);
    gemm_f16<<<dim3(4,64),256,GSMEM>>>(fhh,DFF,fw2h,DFF,fin_b2,4,
        px,xh,nullptr,nullptr,DMODEL,sqrtd,ppe);

    for(int l=0;l<NLAYER;l++){
        size_t w5=(size_t)l*DMODEL*DMODEL;
        size_t wqkv=(size_t)l*1536*DMODEL;
        size_t wf1=(size_t)l*DFF*DMODEL, wf2=(size_t)l*DMODEL*DFF;

        gemm_f16<<<dim3(12,64),256,GSMEM>>>(xh,DMODEL,wqkvh+wqkv,DMODEL,
            pbqkv+l*1536,5,nullptr,qh,kh,vth,DMODEL,0.f,nullptr);

        qk_kernel<<<dim3(4,4,BH),256,QSMEM>>>(qh,kh,psc,scale);
        softmax_kernel<<<BH*SEQ,128>>>(psc,phh,psumr);
        av_f16<<<dim3(4,BH),256,ASMEM>>>(phh,vth,psumr,chh);

        gemm_f16<<<dim3(4,64),256,GSMEM>>>(chh,DMODEL,woh+w5,DMODEL,bo+l*DMODEL,3,
            ptmp,nullptr,nullptr,nullptr,DMODEL,0.f,nullptr);
        ln_kernel<<<MTOK,128>>>(px,ptmp,n1s+l*DMODEL,n1b+l*DMODEL,px,xh);

        gemm_f16<<<dim3(16,64),256,GSMEM>>>(xh,DMODEL,f1h+wf1,DMODEL,ffb1+l*DFF,1,
            nullptr,fhh,nullptr,nullptr,DFF,0.f,nullptr);
        gemm_f16<<<dim3(4,64),256,GSMEM>>>(fhh,DFF,f2h+wf2,DFF,ffb2+l*DMODEL,3,
            ptmp,nullptr,nullptr,nullptr,DMODEL,0.f,nullptr);

        float* lnout=(l==NLAYER-1)?out:px;
        ln_kernel<<<MTOK,128>>>(px,ptmp,n2s+l*DMODEL,n2b+l*DMODEL,lnout,xh);
    }
}

// round 13
// speedup vs baseline: 2.3793x; 1.2518x over previous
#include <cuda_runtime.h>
#include <cuda_fp16.h>
#include <cstdint>
#include <math.h>

#define BATCH 8
#define SEQ 512
#define DMODEL 512
#define NHEAD 8
#define DHEAD 64
#define DFF 2048
#define NLAYER 6
#define DIN 64
#define MTOK (BATCH*SEQ)
#define BH (BATCH*NHEAD)
typedef __half f16;

#define TROW 144   // 72 f16/row, conflict-free ldmatrix

__device__ __forceinline__ uint32_t smem_u32(const void* p){
    uint32_t a; asm("{ .reg .u64 t; cvta.to.shared.u64 t, %1; cvt.u32.u64 %0, t; }":"=r"(a):"l"(p)); return a;
}
__device__ __forceinline__ void ldsm4(uint32_t* r, uint32_t a){
    asm volatile("ldmatrix.sync.aligned.m8n8.x4.shared.b16 {%0,%1,%2,%3}, [%4];"
        : "=r"(r[0]),"=r"(r[1]),"=r"(r[2]),"=r"(r[3]) : "r"(a));
}
__device__ __forceinline__ void mma16816(float* d, const uint32_t* a, const uint32_t* b){
    asm volatile("mma.sync.aligned.m16n8k16.row.col.f32.f16.f16.f32 "
        "{%0,%1,%2,%3}, {%4,%5,%6,%7}, {%8,%9}, {%0,%1,%2,%3};"
        : "+f"(d[0]),"+f"(d[1]),"+f"(d[2]),"+f"(d[3])
        : "r"(a[0]),"r"(a[1]),"r"(a[2]),"r"(a[3]),"r"(b[0]),"r"(b[1]));
}
__device__ __forceinline__ uint32_t packh2(float a, float b){
    __half2 h=__floats2half2_rn(a,b); return *(uint32_t*)&h;
}
#define CP16(dst,src) asm volatile("cp.async.cg.shared.global [%0], [%1], 16;"::"r"(dst),"l"(src))
#define CP_COMMIT() asm volatile("cp.async.commit_group;":::"memory")
#define CP_WAIT0() asm volatile("cp.async.wait_group 0;":::"memory")
#define CP_WAIT1() asm volatile("cp.async.wait_group 1;":::"memory")

// ---------- scratch ----------
__device__ float g_pe[SEQ*DMODEL];
__device__ float g_x[MTOK*DMODEL];
__device__ float g_tmp[MTOK*DMODEL];
__device__ float g_bqkv[NLAYER*1536];
__device__ f16 g_srch[MTOK*DIN];
__device__ f16 g_xh[MTOK*DMODEL];
__device__ f16 g_qh[MTOK*DMODEL];
__device__ f16 g_kh[MTOK*DMODEL];
__device__ f16 g_vth[BH*DHEAD*SEQ];
__device__ f16 g_ch[MTOK*DMODEL];
__device__ f16 g_fh[MTOK*DFF];
__device__ f16 g_fw1h[DFF*DIN];
__device__ f16 g_fw2h[DMODEL*DFF];
__device__ f16 g_wqkvh[NLAYER*1536*DMODEL];
__device__ f16 g_woh[NLAYER*DMODEL*DMODEL];
__device__ f16 g_f1h[NLAYER*DFF*DMODEL];
__device__ f16 g_f2h[NLAYER*DMODEL*DFF];

// ---------- weight transpose (hi only) ----------
__device__ __forceinline__ void do_tsplit(const float* __restrict__ W, f16* __restrict__ Oh,
                                          int K, int N, int z, int bx, int by, size_t lstride){
    __shared__ float t[32][33];
    const float* w=W+(size_t)z*K*N;
    f16* oh=Oh+(size_t)z*lstride;
    int n0=bx*32, k0=by*32, tx=threadIdx.x, ty=threadIdx.y;
#pragma unroll
    for(int i=0;i<32;i+=8) t[ty+i][tx]=w[(size_t)(k0+ty+i)*N+n0+tx];
    __syncthreads();
#pragma unroll
    for(int i=0;i<32;i+=8)
        oh[(size_t)(n0+ty+i)*K+k0+tx]=__float2half_rn(t[tx][ty+i]);
}
#define QKVSTRIDE ((size_t)1536*DMODEL)
__global__ void tsplit_all(const float* fin_w1, const float* fin_w2,
    const float* wq, const float* wk, const float* wv, const float* wo,
    const float* ffw1, const float* ffw2,
    f16* fw1h, f16* fw2h, f16* wqkvh, f16* woh, f16* f1h, f16* f2h){
    int bid=blockIdx.x;
    if(bid<128){ int i=bid; do_tsplit(fin_w1,fw1h,DIN,DFF,0,i%64,i/64,0); return; } bid-=128;
    if(bid<1024){ int i=bid; do_tsplit(fin_w2,fw2h,DFF,DMODEL,0,i%16,i/16,0); return; } bid-=1024;
    if(bid<1536){ int i=bid; do_tsplit(wq,wqkvh,        DMODEL,DMODEL,i/256,(i%256)%16,(i%256)/16,QKVSTRIDE); return; } bid-=1536;
    if(bid<1536){ int i=bid; do_tsplit(wk,wqkvh+262144, DMODEL,DMODEL,i/256,(i%256)%16,(i%256)/16,QKVSTRIDE); return; } bid-=1536;
    if(bid<1536){ int i=bid; do_tsplit(wv,wqkvh+524288, DMODEL,DMODEL,i/256,(i%256)%16,(i%256)/16,QKVSTRIDE); return; } bid-=1536;
    if(bid<1536){ int i=bid; do_tsplit(wo,woh,DMODEL,DMODEL,i/256,(i%256)%16,(i%256)/16,(size_t)DMODEL*DMODEL); return; } bid-=1536;
    if(bid<6144){ int i=bid; do_tsplit(ffw1,f1h,DMODEL,DFF,i/1024,(i%1024)%64,(i%1024)/64,(size_t)DMODEL*DFF); return; } bid-=6144;
    { int i=bid; do_tsplit(ffw2,f2h,DFF,DMODEL,i/1024,(i%1024)%16,(i%1024)/16,(size_t)DMODEL*DFF); }
}
#define TSPLIT_BLOCKS (128+1024+4*1536+6144+6144)

#define SRCBLK ((MTOK*DIN+255)/256)
__global__ void prep_misc(float* __restrict__ pe, const float* __restrict__ src,
                          f16* __restrict__ sh,
                          const float* __restrict__ bq, const float* __restrict__ bk,
                          const float* __restrict__ bv, float* __restrict__ bqkv){
    int bid=blockIdx.x, t=threadIdx.x;
    if(bid<SEQ){
        float dv=expf(-(float)(2*t)*(logf(10000.0f)/(float)DMODEL));
        float a=(float)bid*dv;
        pe[bid*DMODEL+2*t]=sinf(a); pe[bid*DMODEL+2*t+1]=cosf(a);
    } else if(bid<SEQ+SRCBLK){
        int i=(bid-SEQ)*256+t;
        if(i<MTOK*DIN) sh[i]=__float2half_rn(src[i]);
    } else {
        int i=(bid-SEQ-SRCBLK)*256+t;
        if(i<NLAYER*1536){
            int l=i/1536, r=i%1536;
            float v = r<512 ? bq[l*512+r] : (r<1024 ? bk[l*512+r-512] : bv[l*512+r-1024]);
            bqkv[i]=v;
        }
    }
}
#define PREP_BLOCKS (SEQ + SRCBLK + (NLAYER*1536+255)/256)

// ---------- cp.async loader: nrows x 64 f16 into TROW-stride smem ----------
__device__ __forceinline__ void load_cp(uint32_t dst, const f16* __restrict__ src,
                                        int row0, int k0, int ld, int nrows){
    for(int idx=threadIdx.x; idx<nrows*8; idx+=256){
        int r=idx>>3, c8=idx&7;
        CP16(dst + r*TROW + c8*16, src + (size_t)(row0+r)*ld + k0 + c8*8);
    }
}

// one K-64 chunk of single-term fp16 mma
template<int MI,int NI>
__device__ __forceinline__ void mma_chunk(uint32_t sa, uint32_t sb,
                                          float (*acc)[4], int lane, int wm, int wn){
    int ar=(lane&7)+((lane>>3)&1)*8, abit=((lane>>4)&1)*8;
    int br=(lane&7)+((lane>>4)&1)*8, bbit=((lane>>3)&1)*8;
#pragma unroll
    for(int kk=0;kk<4;kk++){
        uint32_t ah[MI][4], bh[NI][2];
        int ac=kk*16+abit, bc=kk*16+bbit;
#pragma unroll
        for(int mi=0;mi<MI;mi++){
            uint32_t off=(uint32_t)((wm+mi*16+ar)*TROW + ac*2);
            ldsm4(ah[mi], sa+off);
        }
#pragma unroll
        for(int nj=0;nj<NI/2;nj++){
            uint32_t off=(uint32_t)((wn+nj*16+br)*TROW + bc*2);
            uint32_t r[4];
            ldsm4(r, sb+off);
            bh[nj*2][0]=r[0]; bh[nj*2][1]=r[1]; bh[nj*2+1][0]=r[2]; bh[nj*2+1][1]=r[3];
        }
#pragma unroll
        for(int mi=0;mi<MI;mi++)
#pragma unroll
            for(int ni=0;ni<NI;ni++) mma16816(acc[mi*NI+ni], ah[mi], bh[ni]);
    }
}

// ---------- GEMM: tile 64x128, K-chunk 64, 2-stage ----------
#define GASZ (64*TROW)
#define GBSZ (128*TROW)
#define GSTG (GASZ+GBSZ)
#define GSMEM (2*GSTG)
// epi: 1 bias,relu->hi | 3 bias->f32 | 4 bias,*alpha,+pe->f32+hi | 5 fused QKV
__global__ __launch_bounds__(256,2)
void gemm_f16(const f16* __restrict__ Ah, int lda,
              const f16* __restrict__ Bh, int K,
              const float* __restrict__ bias, int epi,
              float* __restrict__ of, f16* __restrict__ oh,
              f16* __restrict__ kh, f16* __restrict__ vh,
              int ldc, float alpha, const float* __restrict__ pe){
    extern __shared__ char smem[];
    uint32_t sb0=smem_u32(smem);
    int tid=threadIdx.x, wid=tid>>5, lane=tid&31;
    int row0=blockIdx.y*64, col0=blockIdx.x*128;
    int wm=(wid>>2)*32, wn=(wid&3)*32;
    float acc[8][4];
#pragma unroll
    for(int i=0;i<8;i++){ acc[i][0]=0;acc[i][1]=0;acc[i][2]=0;acc[i][3]=0; }
    int NC=K/64;
    {
        load_cp(sb0,      Ah,row0,0,lda,64);
        load_cp(sb0+GASZ, Bh,col0,0,K,128);
        CP_COMMIT();
    }
    for(int kc=0;kc<NC;kc++){
        if(kc+1<NC){
            uint32_t s=sb0+((kc+1)&1)*GSTG;
            int k0=(kc+1)*64;
            load_cp(s,      Ah,row0,k0,lda,64);
            load_cp(s+GASZ, Bh,col0,k0,K,128);
            CP_COMMIT();
            CP_WAIT1();
        } else CP_WAIT0();
        __syncthreads();
        uint32_t s=sb0+(kc&1)*GSTG;
        mma_chunk<2,4>(s,s+GASZ,acc,lane,wm,wn);
        __syncthreads();
    }
    int gid=lane>>2, tig=lane&3;
#pragma unroll
    for(int mi=0;mi<2;mi++)
#pragma unroll
    for(int ni=0;ni<4;ni++){
        float* d=acc[mi*4+ni];
#pragma unroll
        for(int hf=0;hf<2;hf++){
            int r=row0+wm+mi*16+gid+hf*8;
            int c=col0+wn+ni*8+tig*2;
            float v0=d[hf*2]+__ldg(&bias[c]), v1=d[hf*2+1]+__ldg(&bias[c+1]);
            if(epi==1){ v0=fmaxf(v0,0.f); v1=fmaxf(v1,0.f); }
            if(epi==4){
                const float* per=pe+(size_t)(r&(SEQ-1))*DMODEL+c;
                v0=v0*alpha+per[0]; v1=v1*alpha+per[1];
            }
            if(epi==3||epi==4) *(float2*)(of+(size_t)r*ldc+c)=make_float2(v0,v1);
            if(epi==1||epi==4){
                __half2 H{__float2half_rn(v0),__float2half_rn(v1)};
                *(__half2*)(oh+(size_t)r*ldc+c)=H;
            }
            if(epi==5){
                __half2 H{__float2half_rn(v0),__float2half_rn(v1)};
                if(c<512){
                    *(__half2*)(oh+(size_t)r*DMODEL+c)=H;
                } else if(c<1024){
                    *(__half2*)(kh+(size_t)r*DMODEL+(c-512))=H;
                } else {
                    int b=r>>9, s=r&(SEQ-1);
#pragma unroll
                    for(int u=0;u<2;u++){
                        int n=(c&511)+u; float v=u?v1:v0;
                        size_t off=((size_t)(b*NHEAD+(n>>6))*DHEAD+(n&63))*SEQ+s;
                        vh[off]=__float2half_rn(v);
                    }
                }
            }
        }
    }
}

// ---------- fused flash attention: 128 q-rows x full 512 keys per CTA ----------
// smem: Q 18432 | stage{K 18432, V0 9216, V1 9216} x2 = 92160
#define FQSZ (128*TROW)
#define FKSZ (128*TROW)
#define FVSZ (64*TROW)
#define FSTG (FKSZ+2*FVSZ)
#define FSMEM (FQSZ+2*FSTG)
__global__ __launch_bounds__(256,1)
void flash_kernel(const f16* __restrict__ qh, const f16* __restrict__ kh,
                  const f16* __restrict__ vth, f16* __restrict__ ch, float scale){
    extern __shared__ char smem[];
    uint32_t sb0=smem_u32(smem);
    int tid=threadIdx.x, wid=tid>>5, lane=tid&31;
    int z=blockIdx.y, b=z>>3, h=z&7;
    int row0=blockIdx.x*128, k0=h*DHEAD;
    int wm=wid*16;
    int gid=lane>>2, tig=lane&3;
    int ar=(lane&7)+((lane>>3)&1)*8, abit=((lane>>4)&1)*8;
    int br=(lane&7)+((lane>>4)&1)*8, bbit=((lane>>3)&1)*8;

    // Q tile + key-chunk 0 (group 1)
    load_cp(sb0, qh, b*SEQ+row0, k0, DMODEL, 128);
    {
        uint32_t s=sb0+FQSZ;
        load_cp(s,          kh, b*SEQ, k0, DMODEL, 128);
        load_cp(s+FKSZ,     vth, z*DHEAD, 0, SEQ, 64);
        load_cp(s+FKSZ+FVSZ,vth, z*DHEAD, 64, SEQ, 64);
    }
    CP_COMMIT();

    float oacc[8][4];
#pragma unroll
    for(int i=0;i<8;i++){ oacc[i][0]=0;oacc[i][1]=0;oacc[i][2]=0;oacc[i][3]=0; }
    float m0=-1e30f, m1=-1e30f, l0=0.f, l1=0.f;

    for(int c=0;c<4;c++){
        if(c+1<4){
            uint32_t s=sb0+FQSZ+((c+1)&1)*FSTG;
            int kb=(c+1)*128;
            load_cp(s,          kh, b*SEQ+kb, k0, DMODEL, 128);
            load_cp(s+FKSZ,     vth, z*DHEAD, kb, SEQ, 64);
            load_cp(s+FKSZ+FVSZ,vth, z*DHEAD, kb+64, SEQ, 64);
            CP_COMMIT();
            CP_WAIT1();
        } else CP_WAIT0();
        __syncthreads();
        uint32_t sK=sb0+FQSZ+(c&1)*FSTG;
        uint32_t sV=sK+FKSZ;

        // S = Q @ K^T  (16 rows x 128 keys per warp)
        float sacc[16][4];
#pragma unroll
        for(int i=0;i<16;i++){ sacc[i][0]=0;sacc[i][1]=0;sacc[i][2]=0;sacc[i][3]=0; }
        uint32_t af[4][4];
#pragma unroll
        for(int kk=0;kk<4;kk++)
            ldsm4(af[kk], sb0 + (uint32_t)((wm+ar)*TROW + (kk*16+abit)*2));
#pragma unroll
        for(int kk=0;kk<4;kk++){
#pragma unroll
            for(int kg=0;kg<8;kg++){
                uint32_t r[4];
                ldsm4(r, sK + (uint32_t)((kg*16+br)*TROW + (kk*16+bbit)*2));
                uint32_t b0[2]={r[0],r[1]}, b1[2]={r[2],r[3]};
                mma16816(sacc[kg*2],   af[kk], b0);
                mma16816(sacc[kg*2+1], af[kk], b1);
            }
        }
        // online softmax (rows gid and gid+8; row lives in one lane-quad)
        float mx0=-1e30f, mx1=-1e30f;
#pragma unroll
        for(int t=0;t<16;t++){
            mx0=fmaxf(mx0,fmaxf(sacc[t][0],sacc[t][1]));
            mx1=fmaxf(mx1,fmaxf(sacc[t][2],sacc[t][3]));
        }
        mx0*=scale; mx1*=scale;
        mx0=fmaxf(mx0,__shfl_xor_sync(0xffffffff,mx0,1));
        mx0=fmaxf(mx0,__shfl_xor_sync(0xffffffff,mx0,2));
        mx1=fmaxf(mx1,__shfl_xor_sync(0xffffffff,mx1,1));
        mx1=fmaxf(mx1,__shfl_xor_sync(0xffffffff,mx1,2));
        float nm0=fmaxf(m0,mx0), nm1=fmaxf(m1,mx1);
        float cr0=__expf(m0-nm0), cr1=__expf(m1-nm1);
        float s0=0.f, s1=0.f;
#pragma unroll
        for(int t=0;t<16;t++){
            float e0=__expf(sacc[t][0]*scale-nm0);
            float e1=__expf(sacc[t][1]*scale-nm0);
            float e2=__expf(sacc[t][2]*scale-nm1);
            float e3=__expf(sacc[t][3]*scale-nm1);
            sacc[t][0]=e0; sacc[t][1]=e1; sacc[t][2]=e2; sacc[t][3]=e3;
            s0+=e0+e1; s1+=e2+e3;
        }
        s0+=__shfl_xor_sync(0xffffffff,s0,1); s0+=__shfl_xor_sync(0xffffffff,s0,2);
        s1+=__shfl_xor_sync(0xffffffff,s1,1); s1+=__shfl_xor_sync(0xffffffff,s1,2);
        l0=l0*cr0+s0; l1=l1*cr1+s1; m0=nm0; m1=nm1;
#pragma unroll
        for(int i=0;i<8;i++){ oacc[i][0]*=cr0; oacc[i][1]*=cr0; oacc[i][2]*=cr1; oacc[i][3]*=cr1; }

        // O += P @ V  (k = 128 keys, n = 64 d)
#pragma unroll
        for(int ks=0;ks<8;ks++){
            uint32_t a[4];
            a[0]=packh2(sacc[2*ks][0],  sacc[2*ks][1]);
            a[1]=packh2(sacc[2*ks][2],  sacc[2*ks][3]);
            a[2]=packh2(sacc[2*ks+1][0],sacc[2*ks+1][1]);
            a[3]=packh2(sacc[2*ks+1][2],sacc[2*ks+1][3]);
            uint32_t sv = sV + (ks>=4 ? FVSZ : 0);
            int kc2=(ks&3)*16;
#pragma unroll
            for(int ng=0;ng<4;ng++){
                uint32_t r[4];
                ldsm4(r, sv + (uint32_t)((ng*16+br)*TROW + (kc2+bbit)*2));
                uint32_t b0[2]={r[0],r[1]}, b1[2]={r[2],r[3]};
                mma16816(oacc[ng*2],   a, b0);
                mma16816(oacc[ng*2+1], a, b1);
            }
        }
        __syncthreads();
    }
    // epilogue
    float li0=1.0f/l0, li1=1.0f/l1;
    int r0=row0+wm+gid, t0=b*SEQ+r0, t1=t0+8;
#pragma unroll
    for(int nt=0;nt<8;nt++){
        int col=k0+nt*8+tig*2;
        __half2 H0{__float2half_rn(oacc[nt][0]*li0),__float2half_rn(oacc[nt][1]*li0)};
        __half2 H1{__float2half_rn(oacc[nt][2]*li1),__float2half_rn(oacc[nt][3]*li1)};
        *(__half2*)(ch+(size_t)t0*DMODEL+col)=H0;
        *(__half2*)(ch+(size_t)t1*DMODEL+col)=H1;
    }
}

// ---------- residual + LN -> f32 + hi ----------
__global__ __launch_bounds__(128)
void ln_kernel(const float* __restrict__ x, const float* __restrict__ res,
               const float* __restrict__ gs, const float* __restrict__ gb,
               float* __restrict__ out, f16* __restrict__ oh){
    __shared__ float red[128];
    int row=blockIdx.x, t=threadIdx.x;
    float4 a=*(const float4*)&x[(size_t)row*DMODEL+t*4];
    float4 r=*(const float4*)&res[(size_t)row*DMODEL+t*4];
    float y0=a.x+r.x, y1=a.y+r.y, y2=a.z+r.z, y3=a.w+r.w;
    red[t]=y0+y1+y2+y3; __syncthreads();
    for(int s=64;s>0;s>>=1){ if(t<s) red[t]+=red[t+s]; __syncthreads(); }
    float mu=red[0]*(1.0f/DMODEL); __syncthreads();
    float d0=y0-mu,d1=y1-mu,d2=y2-mu,d3=y3-mu;
    red[t]=d0*d0+d1*d1+d2*d2+d3*d3; __syncthreads();
    for(int s=64;s>0;s>>=1){ if(t<s) red[t]+=red[t+s]; __syncthreads(); }
    float k=rsqrtf(red[0]*(1.0f/DMODEL)+1e-5f);
    float4 sv=*(const float4*)&gs[t*4], bv=*(const float4*)&gb[t*4];
    float o0=d0*k*sv.x+bv.x, o1=d1*k*sv.y+bv.y, o2=d2*k*sv.z+bv.z, o3=d3*k*sv.w+bv.w;
    *(float4*)&out[(size_t)row*DMODEL+t*4]=make_float4(o0,o1,o2,o3);
    size_t off=(size_t)row*DMODEL+t*4;
    __half2 H0{__float2half_rn(o0),__float2half_rn(o1)};
    __half2 H1{__float2half_rn(o2),__float2half_rn(o3)};
    *(__half2*)(oh+off)=H0; *(__half2*)(oh+off+2)=H1;
}

// ---------- host ----------
#define GETP(sym,p,T) do{ void* _t; cudaGetSymbolAddress(&_t,sym); p=(T*)_t; }while(0)

extern "C" void kernel_launch(void* const* d_in, const int* in_sizes, int n_in,
                              void* d_out, int out_size){
    const float* source=(const float*)d_in[0];
    const float* fin_w1=(const float*)d_in[2];
    const float* fin_b1=(const float*)d_in[3];
    const float* fin_w2=(const float*)d_in[4];
    const float* fin_b2=(const float*)d_in[5];
    const float* wq=(const float*)d_in[6];  const float* bq=(const float*)d_in[7];
    const float* wk=(const float*)d_in[8];  const float* bk=(const float*)d_in[9];
    const float* wv=(const float*)d_in[10]; const float* bvv=(const float*)d_in[11];
    const float* wo=(const float*)d_in[12]; const float* bo=(const float*)d_in[13];
    const float* n1s=(const float*)d_in[14]; const float* n1b=(const float*)d_in[15];
    const float* ffw1=(const float*)d_in[16]; const float* ffb1=(const float*)d_in[17];
    const float* ffw2=(const float*)d_in[18]; const float* ffb2=(const float*)d_in[19];
    const float* n2s=(const float*)d_in[20]; const float* n2b=(const float*)d_in[21];
    float* out=(float*)d_out;

    float *ppe,*px,*ptmp,*pbqkv;
    GETP(g_pe,ppe,float); GETP(g_x,px,float); GETP(g_tmp,ptmp,float); GETP(g_bqkv,pbqkv,float);
    f16 *srch,*xh,*qh,*kh,*vth,*chh,*fhh;
    GETP(g_srch,srch,f16); GETP(g_xh,xh,f16);
    GETP(g_qh,qh,f16); GETP(g_kh,kh,f16); GETP(g_vth,vth,f16);
    GETP(g_ch,chh,f16); GETP(g_fh,fhh,f16);
    f16 *fw1h,*fw2h,*wqkvh,*woh,*f1h,*f2h;
    GETP(g_fw1h,fw1h,f16); GETP(g_fw2h,fw2h,f16);
    GETP(g_wqkvh,wqkvh,f16); GETP(g_woh,woh,f16);
    GETP(g_f1h,f1h,f16); GETP(g_f2h,f2h,f16);

    cudaFuncSetAttribute(gemm_f16,     cudaFuncAttributeMaxDynamicSharedMemorySize, GSMEM);
    cudaFuncSetAttribute(flash_kernel, cudaFuncAttributeMaxDynamicSharedMemorySize, FSMEM);

    const float sqrtd=22.627416998f, scale=0.044194173824f;

    tsplit_all<<<TSPLIT_BLOCKS, dim3(32,8)>>>(fin_w1,fin_w2,wq,wk,wv,wo,ffw1,ffw2,
        fw1h,fw2h,wqkvh,woh,f1h,f2h);
    prep_misc<<<PREP_BLOCKS,256>>>(ppe,source,srch,bq,bk,bvv,pbqkv);

    // input FFN
    gemm_f16<<<dim3(16,64),256,GSMEM>>>(srch,DIN,fw1h,DIN,fin_b1,1,
        nullptr,fhh,nullptr,nullptr,DFF,0.f,nullptr);
    gemm_f16<<<dim3(4,64),256,GSMEM>>>(fhh,DFF,fw2h,DFF,fin_b2,4,
        px,xh,nullptr,nullptr,DMODEL,sqrtd,ppe);

    for(int l=0;l<NLAYER;l++){
        size_t w5=(size_t)l*DMODEL*DMODEL;
        size_t wqkv=(size_t)l*1536*DMODEL;
        size_t wf1=(size_t)l*DFF*DMODEL, wf2=(size_t)l*DMODEL*DFF;

        gemm_f16<<<dim3(12,64),256,GSMEM>>>(xh,DMODEL,wqkvh+wqkv,DMODEL,
            pbqkv+l*1536,5,nullptr,qh,kh,vth,DMODEL,0.f,nullptr);

        flash_kernel<<<dim3(4,BH),256,FSMEM>>>(qh,kh,vth,chh,scale);

        gemm_f16<<<dim3(4,64),256,GSMEM>>>(chh,DMODEL,woh+w5,DMODEL,bo+l*DMODEL,3,
            ptmp,nullptr,nullptr,nullptr,DMODEL,0.f,nullptr);
        ln_kernel<<<MTOK,128>>>(px,ptmp,n1s+l*DMODEL,n1b+l*DMODEL,px,xh);

        gemm_f16<<<dim3(16,64),256,GSMEM>>>(xh,DMODEL,f1h+wf1,DMODEL,ffb1+l*DFF,1,
            nullptr,fhh,nullptr,nullptr,DFF,0.f,nullptr);
        gemm_f16<<<dim3(4,64),256,GSMEM>>>(fhh,DFF,f2h+wf2,DFF,ffb2+l*DMODEL,3,
            ptmp,nullptr,nullptr,nullptr,DMODEL,0.f,nullptr);

        float* lnout=(l==NLAYER-1)?out:px;
        ln_kernel<<<MTOK,128>>>(px,ptmp,n2s+l*DMODEL,n2b+l*DMODEL,lnout,xh);
    }
}

// round 14
// speedup vs baseline: 2.5285x; 1.0627x over previous
#include <cuda_runtime.h>
#include <cuda_fp16.h>
#include <cstdint>
#include <math.h>

#define BATCH 8
#define SEQ 512
#define DMODEL 512
#define NHEAD 8
#define DHEAD 64
#define DFF 2048
#define NLAYER 6
#define DIN 64
#define MTOK (BATCH*SEQ)
#define BH (BATCH*NHEAD)
typedef __half f16;

#define TROW 144

__device__ __forceinline__ uint32_t smem_u32(const void* p){
    uint32_t a; asm("{ .reg .u64 t; cvta.to.shared.u64 t, %1; cvt.u32.u64 %0, t; }":"=r"(a):"l"(p)); return a;
}
__device__ __forceinline__ void ldsm4(uint32_t* r, uint32_t a){
    asm volatile("ldmatrix.sync.aligned.m8n8.x4.shared.b16 {%0,%1,%2,%3}, [%4];"
        : "=r"(r[0]),"=r"(r[1]),"=r"(r[2]),"=r"(r[3]) : "r"(a));
}
__device__ __forceinline__ void mma16816(float* d, const uint32_t* a, const uint32_t* b){
    asm volatile("mma.sync.aligned.m16n8k16.row.col.f32.f16.f16.f32 "
        "{%0,%1,%2,%3}, {%4,%5,%6,%7}, {%8,%9}, {%0,%1,%2,%3};"
        : "+f"(d[0]),"+f"(d[1]),"+f"(d[2]),"+f"(d[3])
        : "r"(a[0]),"r"(a[1]),"r"(a[2]),"r"(a[3]),"r"(b[0]),"r"(b[1]));
}
__device__ __forceinline__ uint32_t packh2(float a, float b){
    __half2 h=__floats2half2_rn(a,b); return *(uint32_t*)&h;
}
#define CP16(dst,src) asm volatile("cp.async.cg.shared.global [%0], [%1], 16;"::"r"(dst),"l"(src))
#define CP_COMMIT() asm volatile("cp.async.commit_group;":::"memory")
#define CP_WAIT0() asm volatile("cp.async.wait_group 0;":::"memory")
#define CP_WAIT1() asm volatile("cp.async.wait_group 1;":::"memory")

// ---------- scratch ----------
__device__ float g_pe[SEQ*DMODEL];
__device__ float g_x[MTOK*DMODEL];
__device__ float g_tmp[MTOK*DMODEL];
__device__ float g_bqkv[NLAYER*1536];
__device__ f16 g_srch[MTOK*DIN];
__device__ f16 g_xh[MTOK*DMODEL];
__device__ f16 g_qh[MTOK*DMODEL];
__device__ f16 g_kh[MTOK*DMODEL];
__device__ f16 g_vth[BH*DHEAD*SEQ];
__device__ f16 g_ch[MTOK*DMODEL];
__device__ f16 g_fh[MTOK*DFF];
__device__ f16 g_fw1h[DFF*DIN];
__device__ f16 g_fw2h[DMODEL*DFF];
__device__ f16 g_wqkvh[NLAYER*1536*DMODEL];
__device__ f16 g_woh[NLAYER*DMODEL*DMODEL];
__device__ f16 g_f1h[NLAYER*DFF*DMODEL];
__device__ f16 g_f2h[NLAYER*DMODEL*DFF];

// ---------- weight transpose (hi only) ----------
__device__ __forceinline__ void do_tsplit(const float* __restrict__ W, f16* __restrict__ Oh,
                                          int K, int N, int z, int bx, int by, size_t lstride){
    __shared__ float t[32][33];
    const float* w=W+(size_t)z*K*N;
    f16* oh=Oh+(size_t)z*lstride;
    int n0=bx*32, k0=by*32, tx=threadIdx.x, ty=threadIdx.y;
#pragma unroll
    for(int i=0;i<32;i+=8) t[ty+i][tx]=w[(size_t)(k0+ty+i)*N+n0+tx];
    __syncthreads();
#pragma unroll
    for(int i=0;i<32;i+=8)
        oh[(size_t)(n0+ty+i)*K+k0+tx]=__float2half_rn(t[tx][ty+i]);
}
#define QKVSTRIDE ((size_t)1536*DMODEL)
__global__ void tsplit_all(const float* fin_w1, const float* fin_w2,
    const float* wq, const float* wk, const float* wv, const float* wo,
    const float* ffw1, const float* ffw2,
    f16* fw1h, f16* fw2h, f16* wqkvh, f16* woh, f16* f1h, f16* f2h){
    int bid=blockIdx.x;
    if(bid<128){ int i=bid; do_tsplit(fin_w1,fw1h,DIN,DFF,0,i%64,i/64,0); return; } bid-=128;
    if(bid<1024){ int i=bid; do_tsplit(fin_w2,fw2h,DFF,DMODEL,0,i%16,i/16,0); return; } bid-=1024;
    if(bid<1536){ int i=bid; do_tsplit(wq,wqkvh,        DMODEL,DMODEL,i/256,(i%256)%16,(i%256)/16,QKVSTRIDE); return; } bid-=1536;
    if(bid<1536){ int i=bid; do_tsplit(wk,wqkvh+262144, DMODEL,DMODEL,i/256,(i%256)%16,(i%256)/16,QKVSTRIDE); return; } bid-=1536;
    if(bid<1536){ int i=bid; do_tsplit(wv,wqkvh+524288, DMODEL,DMODEL,i/256,(i%256)%16,(i%256)/16,QKVSTRIDE); return; } bid-=1536;
    if(bid<1536){ int i=bid; do_tsplit(wo,woh,DMODEL,DMODEL,i/256,(i%256)%16,(i%256)/16,(size_t)DMODEL*DMODEL); return; } bid-=1536;
    if(bid<6144){ int i=bid; do_tsplit(ffw1,f1h,DMODEL,DFF,i/1024,(i%1024)%64,(i%1024)/64,(size_t)DMODEL*DFF); return; } bid-=6144;
    { int i=bid; do_tsplit(ffw2,f2h,DFF,DMODEL,i/1024,(i%1024)%16,(i%1024)/16,(size_t)DMODEL*DFF); }
}
#define TSPLIT_BLOCKS (128+1024+4*1536+6144+6144)

#define SRCBLK ((MTOK*DIN+255)/256)
__global__ void prep_misc(float* __restrict__ pe, const float* __restrict__ src,
                          f16* __restrict__ sh,
                          const float* __restrict__ bq, const float* __restrict__ bk,
                          const float* __restrict__ bv, float* __restrict__ bqkv){
    int bid=blockIdx.x, t=threadIdx.x;
    if(bid<SEQ){
        float dv=expf(-(float)(2*t)*(logf(10000.0f)/(float)DMODEL));
        float a=(float)bid*dv;
        pe[bid*DMODEL+2*t]=sinf(a); pe[bid*DMODEL+2*t+1]=cosf(a);
    } else if(bid<SEQ+SRCBLK){
        int i=(bid-SEQ)*256+t;
        if(i<MTOK*DIN) sh[i]=__float2half_rn(src[i]);
    } else {
        int i=(bid-SEQ-SRCBLK)*256+t;
        if(i<NLAYER*1536){
            int l=i/1536, r=i%1536;
            float v = r<512 ? bq[l*512+r] : (r<1024 ? bk[l*512+r-512] : bv[l*512+r-1024]);
            bqkv[i]=v;
        }
    }
}
#define PREP_BLOCKS (SEQ + SRCBLK + (NLAYER*1536+255)/256)

// ---------- cp.async loader ----------
__device__ __forceinline__ void load_cp(uint32_t dst, const f16* __restrict__ src,
                                        int row0, int k0, int ld, int nrows){
    for(int idx=threadIdx.x; idx<nrows*8; idx+=256){
        int r=idx>>3, c8=idx&7;
        CP16(dst + r*TROW + c8*16, src + (size_t)(row0+r)*ld + k0 + c8*8);
    }
}

// one K-64 chunk of single-term fp16 mma
template<int MI,int NI>
__device__ __forceinline__ void mma_chunk(uint32_t sa, uint32_t sb,
                                          float (*acc)[4], int lane, int wm, int wn){
    int ar=(lane&7)+((lane>>3)&1)*8, abit=((lane>>4)&1)*8;
    int br=(lane&7)+((lane>>4)&1)*8, bbit=((lane>>3)&1)*8;
#pragma unroll
    for(int kk=0;kk<4;kk++){
        uint32_t ah[MI][4], bh[NI][2];
        int ac=kk*16+abit, bc=kk*16+bbit;
#pragma unroll
        for(int mi=0;mi<MI;mi++){
            uint32_t off=(uint32_t)((wm+mi*16+ar)*TROW + ac*2);
            ldsm4(ah[mi], sa+off);
        }
#pragma unroll
        for(int nj=0;nj<NI/2;nj++){
            uint32_t off=(uint32_t)((wn+nj*16+br)*TROW + bc*2);
            uint32_t r[4];
            ldsm4(r, sb+off);
            bh[nj*2][0]=r[0]; bh[nj*2][1]=r[1]; bh[nj*2+1][0]=r[2]; bh[nj*2+1][1]=r[3];
        }
#pragma unroll
        for(int mi=0;mi<MI;mi++)
#pragma unroll
            for(int ni=0;ni<NI;ni++) mma16816(acc[mi*NI+ni], ah[mi], bh[ni]);
    }
}

// ---------- GEMM: tile (MI*32)x128, K-chunk 64, 2-stage, 2 CTAs/SM ----------
// epi: 1 bias,relu->hi | 3 bias->f32 | 4 bias,*alpha,+pe->f32+hi | 5 fused QKV
template<int MI>
__global__ __launch_bounds__(256,2)
void gemm_f16(const f16* __restrict__ Ah, int lda,
              const f16* __restrict__ Bh, int K,
              const float* __restrict__ bias, int epi,
              float* __restrict__ of, f16* __restrict__ oh,
              f16* __restrict__ kh, f16* __restrict__ vh,
              int ldc, float alpha, const float* __restrict__ pe){
    constexpr int TM = MI*32;
    constexpr int ASZ = TM*TROW;
    constexpr int BSZ = 128*TROW;
    constexpr int STG = ASZ+BSZ;
    extern __shared__ char smem[];
    uint32_t sb0=smem_u32(smem);
    int tid=threadIdx.x, wid=tid>>5, lane=tid&31;
    int row0=blockIdx.y*TM, col0=blockIdx.x*128;
    int wm=(wid>>2)*(MI*16), wn=(wid&3)*32;
    float acc[MI*4][4];
#pragma unroll
    for(int i=0;i<MI*4;i++){ acc[i][0]=0;acc[i][1]=0;acc[i][2]=0;acc[i][3]=0; }
    int NC=K/64;
    {
        load_cp(sb0,     Ah,row0,0,lda,TM);
        load_cp(sb0+ASZ, Bh,col0,0,K,128);
        CP_COMMIT();
    }
    for(int kc=0;kc<NC;kc++){
        if(kc+1<NC){
            uint32_t s=sb0+((kc+1)&1)*STG;
            int k0=(kc+1)*64;
            load_cp(s,     Ah,row0,k0,lda,TM);
            load_cp(s+ASZ, Bh,col0,k0,K,128);
            CP_COMMIT();
            CP_WAIT1();
        } else CP_WAIT0();
        __syncthreads();
        uint32_t s=sb0+(kc&1)*STG;
        mma_chunk<MI,4>(s,s+ASZ,acc,lane,wm,wn);
        __syncthreads();
    }
    int gid=lane>>2, tig=lane&3;
#pragma unroll
    for(int mi=0;mi<MI;mi++)
#pragma unroll
    for(int ni=0;ni<4;ni++){
        float* d=acc[mi*4+ni];
#pragma unroll
        for(int hf=0;hf<2;hf++){
            int r=row0+wm+mi*16+gid+hf*8;
            int c=col0+wn+ni*8+tig*2;
            float v0=d[hf*2]+__ldg(&bias[c]), v1=d[hf*2+1]+__ldg(&bias[c+1]);
            if(epi==1){ v0=fmaxf(v0,0.f); v1=fmaxf(v1,0.f); }
            if(epi==4){
                const float* per=pe+(size_t)(r&(SEQ-1))*DMODEL+c;
                v0=v0*alpha+per[0]; v1=v1*alpha+per[1];
            }
            if(epi==3||epi==4) *(float2*)(of+(size_t)r*ldc+c)=make_float2(v0,v1);
            if(epi==1||epi==4){
                __half2 H{__float2half_rn(v0),__float2half_rn(v1)};
                *(__half2*)(oh+(size_t)r*ldc+c)=H;
            }
            if(epi==5){
                __half2 H{__float2half_rn(v0),__float2half_rn(v1)};
                if(c<512){
                    *(__half2*)(oh+(size_t)r*DMODEL+c)=H;
                } else if(c<1024){
                    *(__half2*)(kh+(size_t)r*DMODEL+(c-512))=H;
                } else {
                    int b=r>>9, s=r&(SEQ-1);
#pragma unroll
                    for(int u=0;u<2;u++){
                        int n=(c&511)+u; float v=u?v1:v0;
                        size_t off=((size_t)(b*NHEAD+(n>>6))*DHEAD+(n&63))*SEQ+s;
                        vh[off]=__float2half_rn(v);
                    }
                }
            }
        }
    }
}
#define GSMEM2 (2*((64*TROW)+(128*TROW)))    // 55296
#define GSMEM4 (2*((128*TROW)+(128*TROW)))   // 73728

// ---------- fused flash attention (unchanged from R13) ----------
#define FQSZ (128*TROW)
#define FKSZ (128*TROW)
#define FVSZ (64*TROW)
#define FSTG (FKSZ+2*FVSZ)
#define FSMEM (FQSZ+2*FSTG)
__global__ __launch_bounds__(256,1)
void flash_kernel(const f16* __restrict__ qh, const f16* __restrict__ kh,
                  const f16* __restrict__ vth, f16* __restrict__ ch, float scale){
    extern __shared__ char smem[];
    uint32_t sb0=smem_u32(smem);
    int tid=threadIdx.x, wid=tid>>5, lane=tid&31;
    int z=blockIdx.y, b=z>>3, h=z&7;
    int row0=blockIdx.x*128, k0=h*DHEAD;
    int wm=wid*16;
    int gid=lane>>2, tig=lane&3;
    int ar=(lane&7)+((lane>>3)&1)*8, abit=((lane>>4)&1)*8;
    int br=(lane&7)+((lane>>4)&1)*8, bbit=((lane>>3)&1)*8;

    load_cp(sb0, qh, b*SEQ+row0, k0, DMODEL, 128);
    {
        uint32_t s=sb0+FQSZ;
        load_cp(s,          kh, b*SEQ, k0, DMODEL, 128);
        load_cp(s+FKSZ,     vth, z*DHEAD, 0, SEQ, 64);
        load_cp(s+FKSZ+FVSZ,vth, z*DHEAD, 64, SEQ, 64);
    }
    CP_COMMIT();

    float oacc[8][4];
#pragma unroll
    for(int i=0;i<8;i++){ oacc[i][0]=0;oacc[i][1]=0;oacc[i][2]=0;oacc[i][3]=0; }
    float m0=-1e30f, m1=-1e30f, l0=0.f, l1=0.f;

    for(int c=0;c<4;c++){
        if(c+1<4){
            uint32_t s=sb0+FQSZ+((c+1)&1)*FSTG;
            int kb=(c+1)*128;
            load_cp(s,          kh, b*SEQ+kb, k0, DMODEL, 128);
            load_cp(s+FKSZ,     vth, z*DHEAD, kb, SEQ, 64);
            load_cp(s+FKSZ+FVSZ,vth, z*DHEAD, kb+64, SEQ, 64);
            CP_COMMIT();
            CP_WAIT1();
        } else CP_WAIT0();
        __syncthreads();
        uint32_t sK=sb0+FQSZ+(c&1)*FSTG;
        uint32_t sV=sK+FKSZ;

        float sacc[16][4];
#pragma unroll
        for(int i=0;i<16;i++){ sacc[i][0]=0;sacc[i][1]=0;sacc[i][2]=0;sacc[i][3]=0; }
        uint32_t af[4][4];
#pragma unroll
        for(int kk=0;kk<4;kk++)
            ldsm4(af[kk], sb0 + (uint32_t)((wm+ar)*TROW + (kk*16+abit)*2));
#pragma unroll
        for(int kk=0;kk<4;kk++){
#pragma unroll
            for(int kg=0;kg<8;kg++){
                uint32_t r[4];
                ldsm4(r, sK + (uint32_t)((kg*16+br)*TROW + (kk*16+bbit)*2));
                uint32_t b0[2]={r[0],r[1]}, b1[2]={r[2],r[3]};
                mma16816(sacc[kg*2],   af[kk], b0);
                mma16816(sacc[kg*2+1], af[kk], b1);
            }
        }
        float mx0=-1e30f, mx1=-1e30f;
#pragma unroll
        for(int t=0;t<16;t++){
            mx0=fmaxf(mx0,fmaxf(sacc[t][0],sacc[t][1]));
            mx1=fmaxf(mx1,fmaxf(sacc[t][2],sacc[t][3]));
        }
        mx0*=scale; mx1*=scale;
        mx0=fmaxf(mx0,__shfl_xor_sync(0xffffffff,mx0,1));
        mx0=fmaxf(mx0,__shfl_xor_sync(0xffffffff,mx0,2));
        mx1=fmaxf(mx1,__shfl_xor_sync(0xffffffff,mx1,1));
        mx1=fmaxf(mx1,__shfl_xor_sync(0xffffffff,mx1,2));
        float nm0=fmaxf(m0,mx0), nm1=fmaxf(m1,mx1);
        float cr0=__expf(m0-nm0), cr1=__expf(m1-nm1);
        float s0=0.f, s1=0.f;
#pragma unroll
        for(int t=0;t<16;t++){
            float e0=__expf(sacc[t][0]*scale-nm0);
            float e1=__expf(sacc[t][1]*scale-nm0);
            float e2=__expf(sacc[t][2]*scale-nm1);
            float e3=__expf(sacc[t][3]*scale-nm1);
            sacc[t][0]=e0; sacc[t][1]=e1; sacc[t][2]=e2; sacc[t][3]=e3;
            s0+=e0+e1; s1+=e2+e3;
        }
        s0+=__shfl_xor_sync(0xffffffff,s0,1); s0+=__shfl_xor_sync(0xffffffff,s0,2);
        s1+=__shfl_xor_sync(0xffffffff,s1,1); s1+=__shfl_xor_sync(0xffffffff,s1,2);
        l0=l0*cr0+s0; l1=l1*cr1+s1; m0=nm0; m1=nm1;
#pragma unroll
        for(int i=0;i<8;i++){ oacc[i][0]*=cr0; oacc[i][1]*=cr0; oacc[i][2]*=cr1; oacc[i][3]*=cr1; }

#pragma unroll
        for(int ks=0;ks<8;ks++){
            uint32_t a[4];
            a[0]=packh2(sacc[2*ks][0],  sacc[2*ks][1]);
            a[1]=packh2(sacc[2*ks][2],  sacc[2*ks][3]);
            a[2]=packh2(sacc[2*ks+1][0],sacc[2*ks+1][1]);
            a[3]=packh2(sacc[2*ks+1][2],sacc[2*ks+1][3]);
            uint32_t sv = sV + (ks>=4 ? FVSZ : 0);
            int kc2=(ks&3)*16;
#pragma unroll
            for(int ng=0;ng<4;ng++){
                uint32_t r[4];
                ldsm4(r, sv + (uint32_t)((ng*16+br)*TROW + (kc2+bbit)*2));
                uint32_t b0[2]={r[0],r[1]}, b1[2]={r[2],r[3]};
                mma16816(oacc[ng*2],   a, b0);
                mma16816(oacc[ng*2+1], a, b1);
            }
        }
        __syncthreads();
    }
    float li0=1.0f/l0, li1=1.0f/l1;
    int r0=row0+wm+gid, t0=b*SEQ+r0, t1=t0+8;
#pragma unroll
    for(int nt=0;nt<8;nt++){
        int col=k0+nt*8+tig*2;
        __half2 H0{__float2half_rn(oacc[nt][0]*li0),__float2half_rn(oacc[nt][1]*li0)};
        __half2 H1{__float2half_rn(oacc[nt][2]*li1),__float2half_rn(oacc[nt][3]*li1)};
        *(__half2*)(ch+(size_t)t0*DMODEL+col)=H0;
        *(__half2*)(ch+(size_t)t1*DMODEL+col)=H1;
    }
}

// ---------- residual + LN -> f32 + hi ----------
__global__ __launch_bounds__(128)
void ln_kernel(const float* __restrict__ x, const float* __restrict__ res,
               const float* __restrict__ gs, const float* __restrict__ gb,
               float* __restrict__ out, f16* __restrict__ oh){
    __shared__ float red[128];
    int row=blockIdx.x, t=threadIdx.x;
    float4 a=*(const float4*)&x[(size_t)row*DMODEL+t*4];
    float4 r=*(const float4*)&res[(size_t)row*DMODEL+t*4];
    float y0=a.x+r.x, y1=a.y+r.y, y2=a.z+r.z, y3=a.w+r.w;
    red[t]=y0+y1+y2+y3; __syncthreads();
    for(int s=64;s>0;s>>=1){ if(t<s) red[t]+=red[t+s]; __syncthreads(); }
    float mu=red[0]*(1.0f/DMODEL); __syncthreads();
    float d0=y0-mu,d1=y1-mu,d2=y2-mu,d3=y3-mu;
    red[t]=d0*d0+d1*d1+d2*d2+d3*d3; __syncthreads();
    for(int s=64;s>0;s>>=1){ if(t<s) red[t]+=red[t+s]; __syncthreads(); }
    float k=rsqrtf(red[0]*(1.0f/DMODEL)+1e-5f);
    float4 sv=*(const float4*)&gs[t*4], bv=*(const float4*)&gb[t*4];
    float o0=d0*k*sv.x+bv.x, o1=d1*k*sv.y+bv.y, o2=d2*k*sv.z+bv.z, o3=d3*k*sv.w+bv.w;
    *(float4*)&out[(size_t)row*DMODEL+t*4]=make_float4(o0,o1,o2,o3);
    size_t off=(size_t)row*DMODEL+t*4;
    __half2 H0{__float2half_rn(o0),__float2half_rn(o1)};
    __half2 H1{__float2half_rn(o2),__float2half_rn(o3)};
    *(__half2*)(oh+off)=H0; *(__half2*)(oh+off+2)=H1;
}

// ---------- host ----------
#define GETP(sym,p,T) do{ void* _t; cudaGetSymbolAddress(&_t,sym); p=(T*)_t; }while(0)

extern "C" void kernel_launch(void* const* d_in, const int* in_sizes, int n_in,
                              void* d_out, int out_size){
    const float* source=(const float*)d_in[0];
    const float* fin_w1=(const float*)d_in[2];
    const float* fin_b1=(const float*)d_in[3];
    const float* fin_w2=(const float*)d_in[4];
    const float* fin_b2=(const float*)d_in[5];
    const float* wq=(const float*)d_in[6];  const float* bq=(const float*)d_in[7];
    const float* wk=(const float*)d_in[8];  const float* bk=(const float*)d_in[9];
    const float* wv=(const float*)d_in[10]; const float* bvv=(const float*)d_in[11];
    const float* wo=(const float*)d_in[12]; const float* bo=(const float*)d_in[13];
    const float* n1s=(const float*)d_in[14]; const float* n1b=(const float*)d_in[15];
    const float* ffw1=(const float*)d_in[16]; const float* ffb1=(const float*)d_in[17];
    const float* ffw2=(const float*)d_in[18]; const float* ffb2=(const float*)d_in[19];
    const float* n2s=(const float*)d_in[20]; const float* n2b=(const float*)d_in[21];
    float* out=(float*)d_out;

    float *ppe,*px,*ptmp,*pbqkv;
    GETP(g_pe,ppe,float); GETP(g_x,px,float); GETP(g_tmp,ptmp,float); GETP(g_bqkv,pbqkv,float);
    f16 *srch,*xh,*qh,*kh,*vth,*chh,*fhh;
    GETP(g_srch,srch,f16); GETP(g_xh,xh,f16);
    GETP(g_qh,qh,f16); GETP(g_kh,kh,f16); GETP(g_vth,vth,f16);
    GETP(g_ch,chh,f16); GETP(g_fh,fhh,f16);
    f16 *fw1h,*fw2h,*wqkvh,*woh,*f1h,*f2h;
    GETP(g_fw1h,fw1h,f16); GETP(g_fw2h,fw2h,f16);
    GETP(g_wqkvh,wqkvh,f16); GETP(g_woh,woh,f16);
    GETP(g_f1h,f1h,f16); GETP(g_f2h,f2h,f16);

    cudaFuncSetAttribute(gemm_f16<2>,  cudaFuncAttributeMaxDynamicSharedMemorySize, GSMEM2);
    cudaFuncSetAttribute(gemm_f16<4>,  cudaFuncAttributeMaxDynamicSharedMemorySize, GSMEM4);
    cudaFuncSetAttribute(flash_kernel, cudaFuncAttributeMaxDynamicSharedMemorySize, FSMEM);

    const float sqrtd=22.627416998f, scale=0.044194173824f;

    tsplit_all<<<TSPLIT_BLOCKS, dim3(32,8)>>>(fin_w1,fin_w2,wq,wk,wv,wo,ffw1,ffw2,
        fw1h,fw2h,wqkvh,woh,f1h,f2h);
    prep_misc<<<PREP_BLOCKS,256>>>(ppe,source,srch,bq,bk,bvv,pbqkv);

    // input FFN
    gemm_f16<4><<<dim3(16,32),256,GSMEM4>>>(srch,DIN,fw1h,DIN,fin_b1,1,
        nullptr,fhh,nullptr,nullptr,DFF,0.f,nullptr);
    gemm_f16<2><<<dim3(4,64),256,GSMEM2>>>(fhh,DFF,fw2h,DFF,fin_b2,4,
        px,xh,nullptr,nullptr,DMODEL,sqrtd,ppe);

    for(int l=0;l<NLAYER;l++){
        size_t w5=(size_t)l*DMODEL*DMODEL;
        size_t wqkv=(size_t)l*1536*DMODEL;
        size_t wf1=(size_t)l*DFF*DMODEL, wf2=(size_t)l*DMODEL*DFF;

        gemm_f16<4><<<dim3(12,32),256,GSMEM4>>>(xh,DMODEL,wqkvh+wqkv,DMODEL,
            pbqkv+l*1536,5,nullptr,qh,kh,vth,DMODEL,0.f,nullptr);

        flash_kernel<<<dim3(4,BH),256,FSMEM>>>(qh,kh,vth,chh,scale);

        gemm_f16<2><<<dim3(4,64),256,GSMEM2>>>(chh,DMODEL,woh+w5,DMODEL,bo+l*DMODEL,3,
            ptmp,nullptr,nullptr,nullptr,DMODEL,0.f,nullptr);
        ln_kernel<<<MTOK,128>>>(px,ptmp,n1s+l*DMODEL,n1b+l*DMODEL,px,xh);

        gemm_f16<4><<<dim3(16,32),256,GSMEM4>>>(xh,DMODEL,f1h+wf1,DMODEL,ffb1+l*DFF,1,
            nullptr,fhh,nullptr,nullptr,DFF,0.f,nullptr);
        gemm_f16<2><<<dim3(4,64),256,GSMEM2>>>(fhh,DFF,f2h+wf2,DFF,ffb2+l*DMODEL,3,
            ptmp,nullptr,nullptr,nullptr,DMODEL,0.f,nullptr);

        float* lnout=(l==NLAYER-1)?out:px;
        ln_kernel<<<MTOK,128>>>(px,ptmp,n2s+l*DMODEL,n2b+l*DMODEL,lnout,xh);
    }
}

// round 15
// speedup vs baseline: 2.5513x; 1.0090x over previous
#include <cuda_runtime.h>
#include <cuda_fp16.h>
#include <cstdint>
#include <math.h>

#define BATCH 8
#define SEQ 512
#define DMODEL 512
#define NHEAD 8
#define DHEAD 64
#define DFF 2048
#define NLAYER 6
#define DIN 64
#define MTOK (BATCH*SEQ)
#define BH (BATCH*NHEAD)
typedef __half f16;

#define TROW 144

__device__ __forceinline__ uint32_t smem_u32(const void* p){
    uint32_t a; asm("{ .reg .u64 t; cvta.to.shared.u64 t, %1; cvt.u32.u64 %0, t; }":"=r"(a):"l"(p)); return a;
}
__device__ __forceinline__ void ldsm4(uint32_t* r, uint32_t a){
    asm volatile("ldmatrix.sync.aligned.m8n8.x4.shared.b16 {%0,%1,%2,%3}, [%4];"
        : "=r"(r[0]),"=r"(r[1]),"=r"(r[2]),"=r"(r[3]) : "r"(a));
}
__device__ __forceinline__ void mma16816(float* d, const uint32_t* a, const uint32_t* b){
    asm volatile("mma.sync.aligned.m16n8k16.row.col.f32.f16.f16.f32 "
        "{%0,%1,%2,%3}, {%4,%5,%6,%7}, {%8,%9}, {%0,%1,%2,%3};"
        : "+f"(d[0]),"+f"(d[1]),"+f"(d[2]),"+f"(d[3])
        : "r"(a[0]),"r"(a[1]),"r"(a[2]),"r"(a[3]),"r"(b[0]),"r"(b[1]));
}
__device__ __forceinline__ uint32_t packh2(float a, float b){
    __half2 h=__floats2half2_rn(a,b); return *(uint32_t*)&h;
}
#define CP16(dst,src) asm volatile("cp.async.cg.shared.global [%0], [%1], 16;"::"r"(dst),"l"(src))
#define CP_COMMIT() asm volatile("cp.async.commit_group;":::"memory")
#define CP_WAIT0() asm volatile("cp.async.wait_group 0;":::"memory")
#define CP_WAIT1() asm volatile("cp.async.wait_group 1;":::"memory")

// ---------- scratch ----------
__device__ float g_pe[SEQ*DMODEL];
__device__ float g_x[MTOK*DMODEL];
__device__ float g_tmp[MTOK*DMODEL];
__device__ float g_bqkv[NLAYER*1536];
__device__ f16 g_srch[MTOK*DIN];
__device__ f16 g_xh[MTOK*DMODEL];
__device__ f16 g_qh[MTOK*DMODEL];
__device__ f16 g_kh[MTOK*DMODEL];
__device__ f16 g_vth[BH*DHEAD*SEQ];
__device__ f16 g_ch[MTOK*DMODEL];
__device__ f16 g_fh[MTOK*DFF];
__device__ f16 g_fw1h[DFF*DIN];
__device__ f16 g_fw2h[DMODEL*DFF];
__device__ f16 g_wqkvh[NLAYER*1536*DMODEL];
__device__ f16 g_woh[NLAYER*DMODEL*DMODEL];
__device__ f16 g_f1h[NLAYER*DFF*DMODEL];
__device__ f16 g_f2h[NLAYER*DMODEL*DFF];

// ---------- weight transpose (hi only) ----------
__device__ __forceinline__ void do_tsplit(const float* __restrict__ W, f16* __restrict__ Oh,
                                          int K, int N, int z, int bx, int by, size_t lstride){
    __shared__ float t[32][33];
    const float* w=W+(size_t)z*K*N;
    f16* oh=Oh+(size_t)z*lstride;
    int n0=bx*32, k0=by*32, tx=threadIdx.x, ty=threadIdx.y;
#pragma unroll
    for(int i=0;i<32;i+=8) t[ty+i][tx]=w[(size_t)(k0+ty+i)*N+n0+tx];
    __syncthreads();
#pragma unroll
    for(int i=0;i<32;i+=8)
        oh[(size_t)(n0+ty+i)*K+k0+tx]=__float2half_rn(t[tx][ty+i]);
}
#define QKVSTRIDE ((size_t)1536*DMODEL)
__global__ void tsplit_all(const float* fin_w1, const float* fin_w2,
    const float* wq, const float* wk, const float* wv, const float* wo,
    const float* ffw1, const float* ffw2,
    f16* fw1h, f16* fw2h, f16* wqkvh, f16* woh, f16* f1h, f16* f2h){
    int bid=blockIdx.x;
    if(bid<128){ int i=bid; do_tsplit(fin_w1,fw1h,DIN,DFF,0,i%64,i/64,0); return; } bid-=128;
    if(bid<1024){ int i=bid; do_tsplit(fin_w2,fw2h,DFF,DMODEL,0,i%16,i/16,0); return; } bid-=1024;
    if(bid<1536){ int i=bid; do_tsplit(wq,wqkvh,        DMODEL,DMODEL,i/256,(i%256)%16,(i%256)/16,QKVSTRIDE); return; } bid-=1536;
    if(bid<1536){ int i=bid; do_tsplit(wk,wqkvh+262144, DMODEL,DMODEL,i/256,(i%256)%16,(i%256)/16,QKVSTRIDE); return; } bid-=1536;
    if(bid<1536){ int i=bid; do_tsplit(wv,wqkvh+524288, DMODEL,DMODEL,i/256,(i%256)%16,(i%256)/16,QKVSTRIDE); return; } bid-=1536;
    if(bid<1536){ int i=bid; do_tsplit(wo,woh,DMODEL,DMODEL,i/256,(i%256)%16,(i%256)/16,(size_t)DMODEL*DMODEL); return; } bid-=1536;
    if(bid<6144){ int i=bid; do_tsplit(ffw1,f1h,DMODEL,DFF,i/1024,(i%1024)%64,(i%1024)/64,(size_t)DMODEL*DFF); return; } bid-=6144;
    { int i=bid; do_tsplit(ffw2,f2h,DFF,DMODEL,i/1024,(i%1024)%16,(i%1024)/16,(size_t)DMODEL*DFF); }
}
#define TSPLIT_BLOCKS (128+1024+4*1536+6144+6144)

#define SRCBLK ((MTOK*DIN+255)/256)
__global__ void prep_misc(float* __restrict__ pe, const float* __restrict__ src,
                          f16* __restrict__ sh,
                          const float* __restrict__ bq, const float* __restrict__ bk,
                          const float* __restrict__ bv, float* __restrict__ bqkv){
    int bid=blockIdx.x, t=threadIdx.x;
    if(bid<SEQ){
        float dv=expf(-(float)(2*t)*(logf(10000.0f)/(float)DMODEL));
        float a=(float)bid*dv;
        pe[bid*DMODEL+2*t]=sinf(a); pe[bid*DMODEL+2*t+1]=cosf(a);
    } else if(bid<SEQ+SRCBLK){
        int i=(bid-SEQ)*256+t;
        if(i<MTOK*DIN) sh[i]=__float2half_rn(src[i]);
    } else {
        int i=(bid-SEQ-SRCBLK)*256+t;
        if(i<NLAYER*1536){
            int l=i/1536, r=i%1536;
            float v = r<512 ? bq[l*512+r] : (r<1024 ? bk[l*512+r-512] : bv[l*512+r-1024]);
            bqkv[i]=v;
        }
    }
}
#define PREP_BLOCKS (SEQ + SRCBLK + (NLAYER*1536+255)/256)

// ---------- cp.async loader ----------
__device__ __forceinline__ void load_cp(uint32_t dst, const f16* __restrict__ src,
                                        int row0, int k0, int ld, int nrows){
    for(int idx=threadIdx.x; idx<nrows*8; idx+=256){
        int r=idx>>3, c8=idx&7;
        CP16(dst + r*TROW + c8*16, src + (size_t)(row0+r)*ld + k0 + c8*8);
    }
}

// one K-64 chunk of single-term fp16 mma
template<int MI,int NI>
__device__ __forceinline__ void mma_chunk(uint32_t sa, uint32_t sb,
                                          float (*acc)[4], int lane, int wm, int wn){
    int ar=(lane&7)+((lane>>3)&1)*8, abit=((lane>>4)&1)*8;
    int br=(lane&7)+((lane>>4)&1)*8, bbit=((lane>>3)&1)*8;
#pragma unroll
    for(int kk=0;kk<4;kk++){
        uint32_t ah[MI][4], bh[NI][2];
        int ac=kk*16+abit, bc=kk*16+bbit;
#pragma unroll
        for(int mi=0;mi<MI;mi++){
            uint32_t off=(uint32_t)((wm+mi*16+ar)*TROW + ac*2);
            ldsm4(ah[mi], sa+off);
        }
#pragma unroll
        for(int nj=0;nj<NI/2;nj++){
            uint32_t off=(uint32_t)((wn+nj*16+br)*TROW + bc*2);
            uint32_t r[4];
            ldsm4(r, sb+off);
            bh[nj*2][0]=r[0]; bh[nj*2][1]=r[1]; bh[nj*2+1][0]=r[2]; bh[nj*2+1][1]=r[3];
        }
#pragma unroll
        for(int mi=0;mi<MI;mi++)
#pragma unroll
            for(int ni=0;ni<NI;ni++) mma16816(acc[mi*NI+ni], ah[mi], bh[ni]);
    }
}

// ---------- GEMM: tile (MI*32)x128, K-chunk 64, 2-stage, 2 CTAs/SM ----------
// epi: 1 bias,relu->hi | 3 bias->f32 | 4 bias,*alpha,+pe->f32+hi | 5 fused QKV
template<int MI>
__global__ __launch_bounds__(256,2)
void gemm_f16(const f16* __restrict__ Ah, int lda,
              const f16* __restrict__ Bh, int K,
              const float* __restrict__ bias, int epi,
              float* __restrict__ of, f16* __restrict__ oh,
              f16* __restrict__ kh, f16* __restrict__ vh,
              int ldc, float alpha, const float* __restrict__ pe){
    constexpr int TM = MI*32;
    constexpr int ASZ = TM*TROW;
    constexpr int BSZ = 128*TROW;
    constexpr int STG = ASZ+BSZ;
    extern __shared__ char smem[];
    uint32_t sb0=smem_u32(smem);
    int tid=threadIdx.x, wid=tid>>5, lane=tid&31;
    int row0=blockIdx.y*TM, col0=blockIdx.x*128;
    int wm=(wid>>2)*(MI*16), wn=(wid&3)*32;
    float acc[MI*4][4];
#pragma unroll
    for(int i=0;i<MI*4;i++){ acc[i][0]=0;acc[i][1]=0;acc[i][2]=0;acc[i][3]=0; }
    int NC=K/64;
    {
        load_cp(sb0,     Ah,row0,0,lda,TM);
        load_cp(sb0+ASZ, Bh,col0,0,K,128);
        CP_COMMIT();
    }
    for(int kc=0;kc<NC;kc++){
        if(kc+1<NC){
            uint32_t s=sb0+((kc+1)&1)*STG;
            int k0=(kc+1)*64;
            load_cp(s,     Ah,row0,k0,lda,TM);
            load_cp(s+ASZ, Bh,col0,k0,K,128);
            CP_COMMIT();
            CP_WAIT1();
        } else CP_WAIT0();
        __syncthreads();
        uint32_t s=sb0+(kc&1)*STG;
        mma_chunk<MI,4>(s,s+ASZ,acc,lane,wm,wn);
        __syncthreads();
    }
    int gid=lane>>2, tig=lane&3;
#pragma unroll
    for(int mi=0;mi<MI;mi++)
#pragma unroll
    for(int ni=0;ni<4;ni++){
        float* d=acc[mi*4+ni];
#pragma unroll
        for(int hf=0;hf<2;hf++){
            int r=row0+wm+mi*16+gid+hf*8;
            int c=col0+wn+ni*8+tig*2;
            float v0=d[hf*2]+__ldg(&bias[c]), v1=d[hf*2+1]+__ldg(&bias[c+1]);
            if(epi==1){ v0=fmaxf(v0,0.f); v1=fmaxf(v1,0.f); }
            if(epi==4){
                const float* per=pe+(size_t)(r&(SEQ-1))*DMODEL+c;
                v0=v0*alpha+per[0]; v1=v1*alpha+per[1];
            }
            if(epi==3||epi==4) *(float2*)(of+(size_t)r*ldc+c)=make_float2(v0,v1);
            if(epi==1||epi==4){
                __half2 H{__float2half_rn(v0),__float2half_rn(v1)};
                *(__half2*)(oh+(size_t)r*ldc+c)=H;
            }
            if(epi==5){
                __half2 H{__float2half_rn(v0),__float2half_rn(v1)};
                if(c<512){
                    *(__half2*)(oh+(size_t)r*DMODEL+c)=H;
                } else if(c<1024){
                    *(__half2*)(kh+(size_t)r*DMODEL+(c-512))=H;
                } else {
                    int b=r>>9, s=r&(SEQ-1);
#pragma unroll
                    for(int u=0;u<2;u++){
                        int n=(c&511)+u; float v=u?v1:v0;
                        size_t off=((size_t)(b*NHEAD+(n>>6))*DHEAD+(n&63))*SEQ+s;
                        vh[off]=__float2half_rn(v);
                    }
                }
            }
        }
    }
}
#define GSMEM2 (2*((64*TROW)+(128*TROW)))    // 55296
#define GSMEM4 (2*((128*TROW)+(128*TROW)))   // 73728

// ---------- fused flash attention: 128 q-rows, 64-key chunks, 2 CTAs/SM ----------
#define FQSZ (128*TROW)      // 18432
#define FKSZ (64*TROW)       // 9216
#define FVSZ (64*TROW)       // 9216
#define FSTG (FKSZ+FVSZ)     // 18432
#define FSMEM (FQSZ+2*FSTG)  // 55296
__global__ __launch_bounds__(256,2)
void flash_kernel(const f16* __restrict__ qh, const f16* __restrict__ kh,
                  const f16* __restrict__ vth, f16* __restrict__ ch, float scale){
    extern __shared__ char smem[];
    uint32_t sb0=smem_u32(smem);
    int tid=threadIdx.x, wid=tid>>5, lane=tid&31;
    int z=blockIdx.y, b=z>>3, h=z&7;
    int row0=blockIdx.x*128, k0=h*DHEAD;
    int wm=wid*16;
    int gid=lane>>2, tig=lane&3;
    int ar=(lane&7)+((lane>>3)&1)*8, abit=((lane>>4)&1)*8;
    int br=(lane&7)+((lane>>4)&1)*8, bbit=((lane>>3)&1)*8;

    load_cp(sb0, qh, b*SEQ+row0, k0, DMODEL, 128);
    {
        uint32_t s=sb0+FQSZ;
        load_cp(s,      kh, b*SEQ, k0, DMODEL, 64);
        load_cp(s+FKSZ, vth, z*DHEAD, 0, SEQ, 64);
    }
    CP_COMMIT();

    float oacc[8][4];
#pragma unroll
    for(int i=0;i<8;i++){ oacc[i][0]=0;oacc[i][1]=0;oacc[i][2]=0;oacc[i][3]=0; }
    float m0=-1e30f, m1=-1e30f, l0=0.f, l1=0.f;
    uint32_t af[4][4];

    for(int c=0;c<8;c++){
        if(c+1<8){
            uint32_t s=sb0+FQSZ+((c+1)&1)*FSTG;
            int kb=(c+1)*64;
            load_cp(s,      kh, b*SEQ+kb, k0, DMODEL, 64);
            load_cp(s+FKSZ, vth, z*DHEAD, kb, SEQ, 64);
            CP_COMMIT();
            CP_WAIT1();
        } else CP_WAIT0();
        __syncthreads();
        uint32_t sK=sb0+FQSZ+(c&1)*FSTG;
        uint32_t sV=sK+FKSZ;
        if(c==0){
#pragma unroll
            for(int kk=0;kk<4;kk++)
                ldsm4(af[kk], sb0 + (uint32_t)((wm+ar)*TROW + (kk*16+abit)*2));
        }

        // S = Q @ K^T  (16 rows x 64 keys per warp)
        float sacc[8][4];
#pragma unroll
        for(int i=0;i<8;i++){ sacc[i][0]=0;sacc[i][1]=0;sacc[i][2]=0;sacc[i][3]=0; }
#pragma unroll
        for(int kk=0;kk<4;kk++){
#pragma unroll
            for(int kg=0;kg<4;kg++){
                uint32_t r[4];
                ldsm4(r, sK + (uint32_t)((kg*16+br)*TROW + (kk*16+bbit)*2));
                uint32_t b0[2]={r[0],r[1]}, b1[2]={r[2],r[3]};
                mma16816(sacc[kg*2],   af[kk], b0);
                mma16816(sacc[kg*2+1], af[kk], b1);
            }
        }
        // online softmax
        float mx0=-1e30f, mx1=-1e30f;
#pragma unroll
        for(int t=0;t<8;t++){
            mx0=fmaxf(mx0,fmaxf(sacc[t][0],sacc[t][1]));
            mx1=fmaxf(mx1,fmaxf(sacc[t][2],sacc[t][3]));
        }
        mx0*=scale; mx1*=scale;
        mx0=fmaxf(mx0,__shfl_xor_sync(0xffffffff,mx0,1));
        mx0=fmaxf(mx0,__shfl_xor_sync(0xffffffff,mx0,2));
        mx1=fmaxf(mx1,__shfl_xor_sync(0xffffffff,mx1,1));
        mx1=fmaxf(mx1,__shfl_xor_sync(0xffffffff,mx1,2));
        float nm0=fmaxf(m0,mx0), nm1=fmaxf(m1,mx1);
        float cr0=__expf(m0-nm0), cr1=__expf(m1-nm1);
        float s0=0.f, s1=0.f;
#pragma unroll
        for(int t=0;t<8;t++){
            float e0=__expf(sacc[t][0]*scale-nm0);
            float e1=__expf(sacc[t][1]*scale-nm0);
            float e2=__expf(sacc[t][2]*scale-nm1);
            float e3=__expf(sacc[t][3]*scale-nm1);
            sacc[t][0]=e0; sacc[t][1]=e1; sacc[t][2]=e2; sacc[t][3]=e3;
            s0+=e0+e1; s1+=e2+e3;
        }
        s0+=__shfl_xor_sync(0xffffffff,s0,1); s0+=__shfl_xor_sync(0xffffffff,s0,2);
        s1+=__shfl_xor_sync(0xffffffff,s1,1); s1+=__shfl_xor_sync(0xffffffff,s1,2);
        l0=l0*cr0+s0; l1=l1*cr1+s1; m0=nm0; m1=nm1;
#pragma unroll
        for(int i=0;i<8;i++){ oacc[i][0]*=cr0; oacc[i][1]*=cr0; oacc[i][2]*=cr1; oacc[i][3]*=cr1; }

        // O += P @ V  (k = 64 keys, n = 64 d)
#pragma unroll
        for(int ks=0;ks<4;ks++){
            uint32_t a[4];
            a[0]=packh2(sacc[2*ks][0],  sacc[2*ks][1]);
            a[1]=packh2(sacc[2*ks][2],  sacc[2*ks][3]);
            a[2]=packh2(sacc[2*ks+1][0],sacc[2*ks+1][1]);
            a[3]=packh2(sacc[2*ks+1][2],sacc[2*ks+1][3]);
#pragma unroll
            for(int ng=0;ng<4;ng++){
                uint32_t r[4];
                ldsm4(r, sV + (uint32_t)((ng*16+br)*TROW + (ks*16+bbit)*2));
                uint32_t b0[2]={r[0],r[1]}, b1[2]={r[2],r[3]};
                mma16816(oacc[ng*2],   a, b0);
                mma16816(oacc[ng*2+1], a, b1);
            }
        }
        __syncthreads();
    }
    float li0=1.0f/l0, li1=1.0f/l1;
    int r0=row0+wm+gid, t0=b*SEQ+r0, t1=t0+8;
#pragma unroll
    for(int nt=0;nt<8;nt++){
        int col=k0+nt*8+tig*2;
        __half2 H0{__float2half_rn(oacc[nt][0]*li0),__float2half_rn(oacc[nt][1]*li0)};
        __half2 H1{__float2half_rn(oacc[nt][2]*li1),__float2half_rn(oacc[nt][3]*li1)};
        *(__half2*)(ch+(size_t)t0*DMODEL+col)=H0;
        *(__half2*)(ch+(size_t)t1*DMODEL+col)=H1;
    }
}

// ---------- residual + LN (one-pass sum/sumsq, single barrier) ----------
__global__ __launch_bounds__(128)
void ln_kernel(const float* __restrict__ x, const float* __restrict__ res,
               const float* __restrict__ gs, const float* __restrict__ gb,
               float* __restrict__ out, f16* __restrict__ oh){
    __shared__ float ws[8];
    int row=blockIdx.x, t=threadIdx.x, lane=t&31, w=t>>5;
    float4 a=*(const float4*)&x[(size_t)row*DMODEL+t*4];
    float4 r=*(const float4*)&res[(size_t)row*DMODEL+t*4];
    float y0=a.x+r.x, y1=a.y+r.y, y2=a.z+r.z, y3=a.w+r.w;
    float s=y0+y1+y2+y3;
    float q=y0*y0+y1*y1+y2*y2+y3*y3;
#pragma unroll
    for(int o=16;o>0;o>>=1){
        s+=__shfl_xor_sync(0xffffffff,s,o);
        q+=__shfl_xor_sync(0xffffffff,q,o);
    }
    if(lane==0){ ws[w]=s; ws[4+w]=q; }
    __syncthreads();
    float tot=ws[0]+ws[1]+ws[2]+ws[3];
    float totq=ws[4]+ws[5]+ws[6]+ws[7];
    float mu=tot*(1.0f/DMODEL);
    float var=totq*(1.0f/DMODEL)-mu*mu;
    float k=rsqrtf(var+1e-5f);
    float4 sv=*(const float4*)&gs[t*4], bv=*(const float4*)&gb[t*4];
    float o0=(y0-mu)*k*sv.x+bv.x, o1=(y1-mu)*k*sv.y+bv.y;
    float o2=(y2-mu)*k*sv.z+bv.z, o3=(y3-mu)*k*sv.w+bv.w;
    *(float4*)&out[(size_t)row*DMODEL+t*4]=make_float4(o0,o1,o2,o3);
    size_t off=(size_t)row*DMODEL+t*4;
    __half2 H0{__float2half_rn(o0),__float2half_rn(o1)};
    __half2 H1{__float2half_rn(o2),__float2half_rn(o3)};
    *(__half2*)(oh+off)=H0; *(__half2*)(oh+off+2)=H1;
}

// ---------- host ----------
#define GETP(sym,p,T) do{ void* _t; cudaGetSymbolAddress(&_t,sym); p=(T*)_t; }while(0)

extern "C" void kernel_launch(void* const* d_in, const int* in_sizes, int n_in,
                              void* d_out, int out_size){
    const float* source=(const float*)d_in[0];
    const float* fin_w1=(const float*)d_in[2];
    const float* fin_b1=(const float*)d_in[3];
    const float* fin_w2=(const float*)d_in[4];
    const float* fin_b2=(const float*)d_in[5];
    const float* wq=(const float*)d_in[6];  const float* bq=(const float*)d_in[7];
    const float* wk=(const float*)d_in[8];  const float* bk=(const float*)d_in[9];
    const float* wv=(const float*)d_in[10]; const float* bvv=(const float*)d_in[11];
    const float* wo=(const float*)d_in[12]; const float* bo=(const float*)d_in[13];
    const float* n1s=(const float*)d_in[14]; const float* n1b=(const float*)d_in[15];
    const float* ffw1=(const float*)d_in[16]; const float* ffb1=(const float*)d_in[17];
    const float* ffw2=(const float*)d_in[18]; const float* ffb2=(const float*)d_in[19];
    const float* n2s=(const float*)d_in[20]; const float* n2b=(const float*)d_in[21];
    float* out=(float*)d_out;

    float *ppe,*px,*ptmp,*pbqkv;
    GETP(g_pe,ppe,float); GETP(g_x,px,float); GETP(g_tmp,ptmp,float); GETP(g_bqkv,pbqkv,float);
    f16 *srch,*xh,*qh,*kh,*vth,*chh,*fhh;
    GETP(g_srch,srch,f16); GETP(g_xh,xh,f16);
    GETP(g_qh,qh,f16); GETP(g_kh,kh,f16); GETP(g_vth,vth,f16);
    GETP(g_ch,chh,f16); GETP(g_fh,fhh,f16);
    f16 *fw1h,*fw2h,*wqkvh,*woh,*f1h,*f2h;
    GETP(g_fw1h,fw1h,f16); GETP(g_fw2h,fw2h,f16);
    GETP(g_wqkvh,wqkvh,f16); GETP(g_woh,woh,f16);
    GETP(g_f1h,f1h,f16); GETP(g_f2h,f2h,f16);

    cudaFuncSetAttribute(gemm_f16<2>,  cudaFuncAttributeMaxDynamicSharedMemorySize, GSMEM2);
    cudaFuncSetAttribute(gemm_f16<4>,  cudaFuncAttributeMaxDynamicSharedMemorySize, GSMEM4);
    cudaFuncSetAttribute(flash_kernel, cudaFuncAttributeMaxDynamicSharedMemorySize, FSMEM);

    const float sqrtd=22.627416998f, scale=0.044194173824f;

    tsplit_all<<<TSPLIT_BLOCKS, dim3(32,8)>>>(fin_w1,fin_w2,wq,wk,wv,wo,ffw1,ffw2,
        fw1h,fw2h,wqkvh,woh,f1h,f2h);
    prep_misc<<<PREP_BLOCKS,256>>>(ppe,source,srch,bq,bk,bvv,pbqkv);

    // input FFN
    gemm_f16<4><<<dim3(16,32),256,GSMEM4>>>(srch,DIN,fw1h,DIN,fin_b1,1,
        nullptr,fhh,nullptr,nullptr,DFF,0.f,nullptr);
    gemm_f16<2><<<dim3(4,64),256,GSMEM2>>>(fhh,DFF,fw2h,DFF,fin_b2,4,
        px,xh,nullptr,nullptr,DMODEL,sqrtd,ppe);

    for(int l=0;l<NLAYER;l++){
        size_t w5=(size_t)l*DMODEL*DMODEL;
        size_t wqkv=(size_t)l*1536*DMODEL;
        size_t wf1=(size_t)l*DFF*DMODEL, wf2=(size_t)l*DMODEL*DFF;

        gemm_f16<2><<<dim3(12,64),256,GSMEM2>>>(xh,DMODEL,wqkvh+wqkv,DMODEL,
            pbqkv+l*1536,5,nullptr,qh,kh,vth,DMODEL,0.f,nullptr);

        flash_kernel<<<dim3(4,BH),256,FSMEM>>>(qh,kh,vth,chh,scale);

        gemm_f16<2><<<dim3(4,64),256,GSMEM2>>>(chh,DMODEL,woh+w5,DMODEL,bo+l*DMODEL,3,
            ptmp,nullptr,nullptr,nullptr,DMODEL,0.f,nullptr);
        ln_kernel<<<MTOK,128>>>(px,ptmp,n1s+l*DMODEL,n1b+l*DMODEL,px,xh);

        gemm_f16<4><<<dim3(16,32),256,GSMEM4>>>(xh,DMODEL,f1h+wf1,DMODEL,ffb1+l*DFF,1,
            nullptr,fhh,nullptr,nullptr,DFF,0.f,nullptr);
        gemm_f16<2><<<dim3(4,64),256,GSMEM2>>>(fhh,DFF,f2h+wf2,DFF,ffb2+l*DMODEL,3,
            ptmp,nullptr,nullptr,nullptr,DMODEL,0.f,nullptr);

        float* lnout=(l==NLAYER-1)?out:px;
        ln_kernel<<<MTOK,128>>>(px,ptmp,n2s+l*DMODEL,n2b+l*DMODEL,lnout,xh);
    }
}

// round 16
// speedup vs baseline: 2.6907x; 1.0546x over previous
#include <cuda_runtime.h>
#include <cuda_fp16.h>
#include <cstdint>
#include <math.h>

#define BATCH 8
#define SEQ 512
#define DMODEL 512
#define NHEAD 8
#define DHEAD 64
#define DFF 2048
#define NLAYER 6
#define DIN 64
#define MTOK (BATCH*SEQ)
#define BH (BATCH*NHEAD)
typedef __half f16;

#define TROW 144

__device__ __forceinline__ uint32_t smem_u32(const void* p){
    uint32_t a; asm("{ .reg .u64 t; cvta.to.shared.u64 t, %1; cvt.u32.u64 %0, t; }":"=r"(a):"l"(p)); return a;
}
__device__ __forceinline__ void ldsm4(uint32_t* r, uint32_t a){
    asm volatile("ldmatrix.sync.aligned.m8n8.x4.shared.b16 {%0,%1,%2,%3}, [%4];"
        : "=r"(r[0]),"=r"(r[1]),"=r"(r[2]),"=r"(r[3]) : "r"(a));
}
__device__ __forceinline__ void mma16816(float* d, const uint32_t* a, const uint32_t* b){
    asm volatile("mma.sync.aligned.m16n8k16.row.col.f32.f16.f16.f32 "
        "{%0,%1,%2,%3}, {%4,%5,%6,%7}, {%8,%9}, {%0,%1,%2,%3};"
        : "+f"(d[0]),"+f"(d[1]),"+f"(d[2]),"+f"(d[3])
        : "r"(a[0]),"r"(a[1]),"r"(a[2]),"r"(a[3]),"r"(b[0]),"r"(b[1]));
}
__device__ __forceinline__ uint32_t packh2(float a, float b){
    __half2 h=__floats2half2_rn(a,b); return *(uint32_t*)&h;
}
#define CP16(dst,src) asm volatile("cp.async.cg.shared.global [%0], [%1], 16;"::"r"(dst),"l"(src))
#define CP_COMMIT() asm volatile("cp.async.commit_group;":::"memory")
#define CP_WAIT0() asm volatile("cp.async.wait_group 0;":::"memory")
#define CP_WAIT1() asm volatile("cp.async.wait_group 1;":::"memory")

// ---------- scratch ----------
__device__ float g_pe[SEQ*DMODEL];
__device__ float g_x[MTOK*DMODEL];
__device__ float g_tmp[MTOK*DMODEL];
__device__ float g_bqkv[NLAYER*1536];
__device__ f16 g_srch[MTOK*DIN];
__device__ f16 g_xh[MTOK*DMODEL];
__device__ f16 g_qh[MTOK*DMODEL];
__device__ f16 g_kh[MTOK*DMODEL];
__device__ f16 g_vth[BH*DHEAD*SEQ];
__device__ f16 g_ch[MTOK*DMODEL];
__device__ f16 g_fh[MTOK*DFF];
__device__ f16 g_fw1h[DFF*DIN];
__device__ f16 g_fw2h[DMODEL*DFF];
__device__ f16 g_wqkvh[NLAYER*1536*DMODEL];
__device__ f16 g_woh[NLAYER*DMODEL*DMODEL];
__device__ f16 g_f1h[NLAYER*DFF*DMODEL];
__device__ f16 g_f2h[NLAYER*DMODEL*DFF];

// ---------- weight transpose (hi only) ----------
__device__ __forceinline__ void do_tsplit(const float* __restrict__ W, f16* __restrict__ Oh,
                                          int K, int N, int z, int bx, int by, size_t lstride){
    __shared__ float t[32][33];
    const float* w=W+(size_t)z*K*N;
    f16* oh=Oh+(size_t)z*lstride;
    int n0=bx*32, k0=by*32, tx=threadIdx.x, ty=threadIdx.y;
#pragma unroll
    for(int i=0;i<32;i+=8) t[ty+i][tx]=w[(size_t)(k0+ty+i)*N+n0+tx];
    __syncthreads();
#pragma unroll
    for(int i=0;i<32;i+=8)
        oh[(size_t)(n0+ty+i)*K+k0+tx]=__float2half_rn(t[tx][ty+i]);
}
#define QKVSTRIDE ((size_t)1536*DMODEL)
__global__ void tsplit_all(const float* fin_w1, const float* fin_w2,
    const float* wq, const float* wk, const float* wv, const float* wo,
    const float* ffw1, const float* ffw2,
    f16* fw1h, f16* fw2h, f16* wqkvh, f16* woh, f16* f1h, f16* f2h){
    int bid=blockIdx.x;
    if(bid<128){ int i=bid; do_tsplit(fin_w1,fw1h,DIN,DFF,0,i%64,i/64,0); return; } bid-=128;
    if(bid<1024){ int i=bid; do_tsplit(fin_w2,fw2h,DFF,DMODEL,0,i%16,i/16,0); return; } bid-=1024;
    if(bid<1536){ int i=bid; do_tsplit(wq,wqkvh,        DMODEL,DMODEL,i/256,(i%256)%16,(i%256)/16,QKVSTRIDE); return; } bid-=1536;
    if(bid<1536){ int i=bid; do_tsplit(wk,wqkvh+262144, DMODEL,DMODEL,i/256,(i%256)%16,(i%256)/16,QKVSTRIDE); return; } bid-=1536;
    if(bid<1536){ int i=bid; do_tsplit(wv,wqkvh+524288, DMODEL,DMODEL,i/256,(i%256)%16,(i%256)/16,QKVSTRIDE); return; } bid-=1536;
    if(bid<1536){ int i=bid; do_tsplit(wo,woh,DMODEL,DMODEL,i/256,(i%256)%16,(i%256)/16,(size_t)DMODEL*DMODEL); return; } bid-=1536;
    if(bid<6144){ int i=bid; do_tsplit(ffw1,f1h,DMODEL,DFF,i/1024,(i%1024)%64,(i%1024)/64,(size_t)DMODEL*DFF); return; } bid-=6144;
    { int i=bid; do_tsplit(ffw2,f2h,DFF,DMODEL,i/1024,(i%1024)%16,(i%1024)/16,(size_t)DMODEL*DFF); }
}
#define TSPLIT_BLOCKS (128+1024+4*1536+6144+6144)

#define SRCBLK ((MTOK*DIN+255)/256)
__global__ void prep_misc(float* __restrict__ pe, const float* __restrict__ src,
                          f16* __restrict__ sh,
                          const float* __restrict__ bq, const float* __restrict__ bk,
                          const float* __restrict__ bv, float* __restrict__ bqkv){
    int bid=blockIdx.x, t=threadIdx.x;
    if(bid<SEQ){
        float dv=expf(-(float)(2*t)*(logf(10000.0f)/(float)DMODEL));
        float a=(float)bid*dv;
        pe[bid*DMODEL+2*t]=sinf(a); pe[bid*DMODEL+2*t+1]=cosf(a);
    } else if(bid<SEQ+SRCBLK){
        int i=(bid-SEQ)*256+t;
        if(i<MTOK*DIN) sh[i]=__float2half_rn(src[i]);
    } else {
        int i=(bid-SEQ-SRCBLK)*256+t;
        if(i<NLAYER*1536){
            int l=i/1536, r=i%1536;
            float v = r<512 ? bq[l*512+r] : (r<1024 ? bk[l*512+r-512] : bv[l*512+r-1024]);
            bqkv[i]=v;
        }
    }
}
#define PREP_BLOCKS (SEQ + SRCBLK + (NLAYER*1536+255)/256)

// ---------- cp.async loader ----------
__device__ __forceinline__ void load_cp(uint32_t dst, const f16* __restrict__ src,
                                        int row0, int k0, int ld, int nrows){
    for(int idx=threadIdx.x; idx<nrows*8; idx+=256){
        int r=idx>>3, c8=idx&7;
        CP16(dst + r*TROW + c8*16, src + (size_t)(row0+r)*ld + k0 + c8*8);
    }
}

// one K-64 chunk of single-term fp16 mma
template<int MI,int NI>
__device__ __forceinline__ void mma_chunk(uint32_t sa, uint32_t sb,
                                          float (*acc)[4], int lane, int wm, int wn){
    int ar=(lane&7)+((lane>>3)&1)*8, abit=((lane>>4)&1)*8;
    int br=(lane&7)+((lane>>4)&1)*8, bbit=((lane>>3)&1)*8;
#pragma unroll
    for(int kk=0;kk<4;kk++){
        uint32_t ah[MI][4], bh[NI][2];
        int ac=kk*16+abit, bc=kk*16+bbit;
#pragma unroll
        for(int mi=0;mi<MI;mi++){
            uint32_t off=(uint32_t)((wm+mi*16+ar)*TROW + ac*2);
            ldsm4(ah[mi], sa+off);
        }
#pragma unroll
        for(int nj=0;nj<NI/2;nj++){
            uint32_t off=(uint32_t)((wn+nj*16+br)*TROW + bc*2);
            uint32_t r[4];
            ldsm4(r, sb+off);
            bh[nj*2][0]=r[0]; bh[nj*2][1]=r[1]; bh[nj*2+1][0]=r[2]; bh[nj*2+1][1]=r[3];
        }
#pragma unroll
        for(int mi=0;mi<MI;mi++)
#pragma unroll
            for(int ni=0;ni<NI;ni++) mma16816(acc[mi*NI+ni], ah[mi], bh[ni]);
    }
}

// ---------- GEMM: tile (MI*32)x128, K-chunk 64, 3-stage, ONE barrier/chunk ----------
// epi: 1 bias,relu->hi | 3 bias->f32 | 4 bias,*alpha,+pe->f32+hi | 5 fused QKV
template<int MI>
__global__ __launch_bounds__(256,2)
void gemm_f16(const f16* __restrict__ Ah, int lda,
              const f16* __restrict__ Bh, int K,
              const float* __restrict__ bias, int epi,
              float* __restrict__ of, f16* __restrict__ oh,
              f16* __restrict__ kh, f16* __restrict__ vh,
              int ldc, float alpha, const float* __restrict__ pe){
    constexpr int TM = MI*32;
    constexpr int ASZ = TM*TROW;
    constexpr int BSZ = 128*TROW;
    constexpr int STG = ASZ+BSZ;
    extern __shared__ char smem[];
    uint32_t sb0=smem_u32(smem);
    int tid=threadIdx.x, wid=tid>>5, lane=tid&31;
    int row0=blockIdx.y*TM, col0=blockIdx.x*128;
    int wm=(wid>>2)*(MI*16), wn=(wid&3)*32;
    float acc[MI*4][4];
#pragma unroll
    for(int i=0;i<MI*4;i++){ acc[i][0]=0;acc[i][1]=0;acc[i][2]=0;acc[i][3]=0; }
    int NC=K/64;
    // prologue: chunks 0,1 into stages 0,1
    {
        load_cp(sb0,     Ah,row0,0,lda,TM);
        load_cp(sb0+ASZ, Bh,col0,0,K,128);
        CP_COMMIT();
        if(NC>1){
            load_cp(sb0+STG,     Ah,row0,64,lda,TM);
            load_cp(sb0+STG+ASZ, Bh,col0,64,K,128);
            CP_COMMIT();
        }
    }
    int st=0;
    for(int kc=0;kc<NC;kc++){
        if(kc+1<NC) CP_WAIT1(); else CP_WAIT0();
        __syncthreads();
        if(kc+2<NC){
            int s2=st+2; if(s2>=3) s2-=3;
            uint32_t s=sb0+s2*STG;
            int k0=(kc+2)*64;
            load_cp(s,     Ah,row0,k0,lda,TM);
            load_cp(s+ASZ, Bh,col0,k0,K,128);
            CP_COMMIT();
        }
        uint32_t s=sb0+st*STG;
        mma_chunk<MI,4>(s,s+ASZ,acc,lane,wm,wn);
        if(++st==3) st=0;
    }
    int gid=lane>>2, tig=lane&3;
#pragma unroll
    for(int mi=0;mi<MI;mi++)
#pragma unroll
    for(int ni=0;ni<4;ni++){
        float* d=acc[mi*4+ni];
#pragma unroll
        for(int hf=0;hf<2;hf++){
            int r=row0+wm+mi*16+gid+hf*8;
            int c=col0+wn+ni*8+tig*2;
            float v0=d[hf*2]+__ldg(&bias[c]), v1=d[hf*2+1]+__ldg(&bias[c+1]);
            if(epi==1){ v0=fmaxf(v0,0.f); v1=fmaxf(v1,0.f); }
            if(epi==4){
                const float* per=pe+(size_t)(r&(SEQ-1))*DMODEL+c;
                v0=v0*alpha+per[0]; v1=v1*alpha+per[1];
            }
            if(epi==3||epi==4) *(float2*)(of+(size_t)r*ldc+c)=make_float2(v0,v1);
            if(epi==1||epi==4){
                __half2 H{__float2half_rn(v0),__float2half_rn(v1)};
                *(__half2*)(oh+(size_t)r*ldc+c)=H;
            }
            if(epi==5){
                __half2 H{__float2half_rn(v0),__float2half_rn(v1)};
                if(c<512){
                    *(__half2*)(oh+(size_t)r*DMODEL+c)=H;
                } else if(c<1024){
                    *(__half2*)(kh+(size_t)r*DMODEL+(c-512))=H;
                } else {
                    int b=r>>9, s=r&(SEQ-1);
#pragma unroll
                    for(int u=0;u<2;u++){
                        int n=(c&511)+u; float v=u?v1:v0;
                        size_t off=((size_t)(b*NHEAD+(n>>6))*DHEAD+(n&63))*SEQ+s;
                        vh[off]=__float2half_rn(v);
                    }
                }
            }
        }
    }
}
#define GSMEM2 (3*((64*TROW)+(128*TROW)))    // 82944
#define GSMEM4 (3*((128*TROW)+(128*TROW)))   // 110592

// ---------- fused flash attention: 128 q-rows, 64-key chunks, 3-stage 1-barrier ----------
#define FQSZ (128*TROW)      // 18432
#define FKSZ (64*TROW)       // 9216
#define FVSZ (64*TROW)       // 9216
#define FSTG (FKSZ+FVSZ)     // 18432
#define FSMEM (FQSZ+3*FSTG)  // 73728
__global__ __launch_bounds__(256,2)
void flash_kernel(const f16* __restrict__ qh, const f16* __restrict__ kh,
                  const f16* __restrict__ vth, f16* __restrict__ ch, float scale){
    extern __shared__ char smem[];
    uint32_t sb0=smem_u32(smem);
    int tid=threadIdx.x, wid=tid>>5, lane=tid&31;
    int z=blockIdx.y, b=z>>3, h=z&7;
    int row0=blockIdx.x*128, k0=h*DHEAD;
    int wm=wid*16;
    int gid=lane>>2, tig=lane&3;
    int ar=(lane&7)+((lane>>3)&1)*8, abit=((lane>>4)&1)*8;
    int br=(lane&7)+((lane>>4)&1)*8, bbit=((lane>>3)&1)*8;

    // prologue: Q + chunk0 into stage0 (group0), chunk1 into stage1 (group1)
    load_cp(sb0, qh, b*SEQ+row0, k0, DMODEL, 128);
    {
        uint32_t s=sb0+FQSZ;
        load_cp(s,      kh, b*SEQ, k0, DMODEL, 64);
        load_cp(s+FKSZ, vth, z*DHEAD, 0, SEQ, 64);
        CP_COMMIT();
        load_cp(s+FSTG,      kh, b*SEQ+64, k0, DMODEL, 64);
        load_cp(s+FSTG+FKSZ, vth, z*DHEAD, 64, SEQ, 64);
        CP_COMMIT();
    }

    float oacc[8][4];
#pragma unroll
    for(int i=0;i<8;i++){ oacc[i][0]=0;oacc[i][1]=0;oacc[i][2]=0;oacc[i][3]=0; }
    float m0=-1e30f, m1=-1e30f, l0=0.f, l1=0.f;
    uint32_t af[4][4];

    int st=0;
    for(int c=0;c<8;c++){
        if(c+1<8) CP_WAIT1(); else CP_WAIT0();
        __syncthreads();
        if(c+2<8){
            int s2=st+2; if(s2>=3) s2-=3;
            uint32_t s=sb0+FQSZ+s2*FSTG;
            int kb=(c+2)*64;
            load_cp(s,      kh, b*SEQ+kb, k0, DMODEL, 64);
            load_cp(s+FKSZ, vth, z*DHEAD, kb, SEQ, 64);
            CP_COMMIT();
        }
        uint32_t sK=sb0+FQSZ+st*FSTG;
        uint32_t sV=sK+FKSZ;
        if(c==0){
#pragma unroll
            for(int kk=0;kk<4;kk++)
                ldsm4(af[kk], sb0 + (uint32_t)((wm+ar)*TROW + (kk*16+abit)*2));
        }

        // S = Q @ K^T
        float sacc[8][4];
#pragma unroll
        for(int i=0;i<8;i++){ sacc[i][0]=0;sacc[i][1]=0;sacc[i][2]=0;sacc[i][3]=0; }
#pragma unroll
        for(int kk=0;kk<4;kk++){
#pragma unroll
            for(int kg=0;kg<4;kg++){
                uint32_t r[4];
                ldsm4(r, sK + (uint32_t)((kg*16+br)*TROW + (kk*16+bbit)*2));
                uint32_t b0[2]={r[0],r[1]}, b1[2]={r[2],r[3]};
                mma16816(sacc[kg*2],   af[kk], b0);
                mma16816(sacc[kg*2+1], af[kk], b1);
            }
        }
        // online softmax
        float mx0=-1e30f, mx1=-1e30f;
#pragma unroll
        for(int t=0;t<8;t++){
            mx0=fmaxf(mx0,fmaxf(sacc[t][0],sacc[t][1]));
            mx1=fmaxf(mx1,fmaxf(sacc[t][2],sacc[t][3]));
        }
        mx0*=scale; mx1*=scale;
        mx0=fmaxf(mx0,__shfl_xor_sync(0xffffffff,mx0,1));
        mx0=fmaxf(mx0,__shfl_xor_sync(0xffffffff,mx0,2));
        mx1=fmaxf(mx1,__shfl_xor_sync(0xffffffff,mx1,1));
        mx1=fmaxf(mx1,__shfl_xor_sync(0xffffffff,mx1,2));
        float nm0=fmaxf(m0,mx0), nm1=fmaxf(m1,mx1);
        float cr0=__expf(m0-nm0), cr1=__expf(m1-nm1);
        float s0=0.f, s1=0.f;
#pragma unroll
        for(int t=0;t<8;t++){
            float e0=__expf(sacc[t][0]*scale-nm0);
            float e1=__expf(sacc[t][1]*scale-nm0);
            float e2=__expf(sacc[t][2]*scale-nm1);
            float e3=__expf(sacc[t][3]*scale-nm1);
            sacc[t][0]=e0; sacc[t][1]=e1; sacc[t][2]=e2; sacc[t][3]=e3;
            s0+=e0+e1; s1+=e2+e3;
        }
        s0+=__shfl_xor_sync(0xffffffff,s0,1); s0+=__shfl_xor_sync(0xffffffff,s0,2);
        s1+=__shfl_xor_sync(0xffffffff,s1,1); s1+=__shfl_xor_sync(0xffffffff,s1,2);
        l0=l0*cr0+s0; l1=l1*cr1+s1; m0=nm0; m1=nm1;
#pragma unroll
        for(int i=0;i<8;i++){ oacc[i][0]*=cr0; oacc[i][1]*=cr0; oacc[i][2]*=cr1; oacc[i][3]*=cr1; }

        // O += P @ V
#pragma unroll
        for(int ks=0;ks<4;ks++){
            uint32_t a[4];
            a[0]=packh2(sacc[2*ks][0],  sacc[2*ks][1]);
            a[1]=packh2(sacc[2*ks][2],  sacc[2*ks][3]);
            a[2]=packh2(sacc[2*ks+1][0],sacc[2*ks+1][1]);
            a[3]=packh2(sacc[2*ks+1][2],sacc[2*ks+1][3]);
#pragma unroll
            for(int ng=0;ng<4;ng++){
                uint32_t r[4];
                ldsm4(r, sV + (uint32_t)((ng*16+br)*TROW + (ks*16+bbit)*2));
                uint32_t b0[2]={r[0],r[1]}, b1[2]={r[2],r[3]};
                mma16816(oacc[ng*2],   a, b0);
                mma16816(oacc[ng*2+1], a, b1);
            }
        }
        if(++st==3) st=0;
    }
    float li0=1.0f/l0, li1=1.0f/l1;
    int r0=row0+wm+gid, t0=b*SEQ+r0, t1=t0+8;
#pragma unroll
    for(int nt=0;nt<8;nt++){
        int col=k0+nt*8+tig*2;
        __half2 H0{__float2half_rn(oacc[nt][0]*li0),__float2half_rn(oacc[nt][1]*li0)};
        __half2 H1{__float2half_rn(oacc[nt][2]*li1),__float2half_rn(oacc[nt][3]*li1)};
        *(__half2*)(ch+(size_t)t0*DMODEL+col)=H0;
        *(__half2*)(ch+(size_t)t1*DMODEL+col)=H1;
    }
}

// ---------- residual + LN (one-pass, single barrier) ----------
__global__ __launch_bounds__(128)
void ln_kernel(const float* __restrict__ x, const float* __restrict__ res,
               const float* __restrict__ gs, const float* __restrict__ gb,
               float* __restrict__ out, f16* __restrict__ oh){
    __shared__ float ws[8];
    int row=blockIdx.x, t=threadIdx.x, lane=t&31, w=t>>5;
    float4 a=*(const float4*)&x[(size_t)row*DMODEL+t*4];
    float4 r=*(const float4*)&res[(size_t)row*DMODEL+t*4];
    float y0=a.x+r.x, y1=a.y+r.y, y2=a.z+r.z, y3=a.w+r.w;
    float s=y0+y1+y2+y3;
    float q=y0*y0+y1*y1+y2*y2+y3*y3;
#pragma unroll
    for(int o=16;o>0;o>>=1){
        s+=__shfl_xor_sync(0xffffffff,s,o);
        q+=__shfl_xor_sync(0xffffffff,q,o);
    }
    if(lane==0){ ws[w]=s; ws[4+w]=q; }
    __syncthreads();
    float tot=ws[0]+ws[1]+ws[2]+ws[3];
    float totq=ws[4]+ws[5]+ws[6]+ws[7];
    float mu=tot*(1.0f/DMODEL);
    float var=totq*(1.0f/DMODEL)-mu*mu;
    float k=rsqrtf(var+1e-5f);
    float4 sv=*(const float4*)&gs[t*4], bv=*(const float4*)&gb[t*4];
    float o0=(y0-mu)*k*sv.x+bv.x, o1=(y1-mu)*k*sv.y+bv.y;
    float o2=(y2-mu)*k*sv.z+bv.z, o3=(y3-mu)*k*sv.w+bv.w;
    *(float4*)&out[(size_t)row*DMODEL+t*4]=make_float4(o0,o1,o2,o3);
    size_t off=(size_t)row*DMODEL+t*4;
    __half2 H0{__float2half_rn(o0),__float2half_rn(o1)};
    __half2 H1{__float2half_rn(o2),__float2half_rn(o3)};
    *(__half2*)(oh+off)=H0; *(__half2*)(oh+off+2)=H1;
}

// ---------- host ----------
#define GETP(sym,p,T) do{ void* _t; cudaGetSymbolAddress(&_t,sym); p=(T*)_t; }while(0)

extern "C" void kernel_launch(void* const* d_in, const int* in_sizes, int n_in,
                              void* d_out, int out_size){
    const float* source=(const float*)d_in[0];
    const float* fin_w1=(const float*)d_in[2];
    const float* fin_b1=(const float*)d_in[3];
    const float* fin_w2=(const float*)d_in[4];
    const float* fin_b2=(const float*)d_in[5];
    const float* wq=(const float*)d_in[6];  const float* bq=(const float*)d_in[7];
    const float* wk=(const float*)d_in[8];  const float* bk=(const float*)d_in[9];
    const float* wv=(const float*)d_in[10]; const float* bvv=(const float*)d_in[11];
    const float* wo=(const float*)d_in[12]; const float* bo=(const float*)d_in[13];
    const float* n1s=(const float*)d_in[14]; const float* n1b=(const float*)d_in[15];
    const float* ffw1=(const float*)d_in[16]; const float* ffb1=(const float*)d_in[17];
    const float* ffw2=(const float*)d_in[18]; const float* ffb2=(const float*)d_in[19];
    const float* n2s=(const float*)d_in[20]; const float* n2b=(const float*)d_in[21];
    float* out=(float*)d_out;

    float *ppe,*px,*ptmp,*pbqkv;
    GETP(g_pe,ppe,float); GETP(g_x,px,float); GETP(g_tmp,ptmp,float); GETP(g_bqkv,pbqkv,float);
    f16 *srch,*xh,*qh,*kh,*vth,*chh,*fhh;
    GETP(g_srch,srch,f16); GETP(g_xh,xh,f16);
    GETP(g_qh,qh,f16); GETP(g_kh,kh,f16); GETP(g_vth,vth,f16);
    GETP(g_ch,chh,f16); GETP(g_fh,fhh,f16);
    f16 *fw1h,*fw2h,*wqkvh,*woh,*f1h,*f2h;
    GETP(g_fw1h,fw1h,f16); GETP(g_fw2h,fw2h,f16);
    GETP(g_wqkvh,wqkvh,f16); GETP(g_woh,woh,f16);
    GETP(g_f1h,f1h,f16); GETP(g_f2h,f2h,f16);

    cudaFuncSetAttribute(gemm_f16<2>,  cudaFuncAttributeMaxDynamicSharedMemorySize, GSMEM2);
    cudaFuncSetAttribute(gemm_f16<4>,  cudaFuncAttributeMaxDynamicSharedMemorySize, GSMEM4);
    cudaFuncSetAttribute(flash_kernel, cudaFuncAttributeMaxDynamicSharedMemorySize, FSMEM);

    const float sqrtd=22.627416998f, scale=0.044194173824f;

    tsplit_all<<<TSPLIT_BLOCKS, dim3(32,8)>>>(fin_w1,fin_w2,wq,wk,wv,wo,ffw1,ffw2,
        fw1h,fw2h,wqkvh,woh,f1h,f2h);
    prep_misc<<<PREP_BLOCKS,256>>>(ppe,source,srch,bq,bk,bvv,pbqkv);

    // input FFN
    gemm_f16<4><<<dim3(16,32),256,GSMEM4>>>(srch,DIN,fw1h,DIN,fin_b1,1,
        nullptr,fhh,nullptr,nullptr,DFF,0.f,nullptr);
    gemm_f16<2><<<dim3(4,64),256,GSMEM2>>>(fhh,DFF,fw2h,DFF,fin_b2,4,
        px,xh,nullptr,nullptr,DMODEL,sqrtd,ppe);

    for(int l=0;l<NLAYER;l++){
        size_t w5=(size_t)l*DMODEL*DMODEL;
        size_t wqkv=(size_t)l*1536*DMODEL;
        size_t wf1=(size_t)l*DFF*DMODEL, wf2=(size_t)l*DMODEL*DFF;

        gemm_f16<4><<<dim3(12,32),256,GSMEM4>>>(xh,DMODEL,wqkvh+wqkv,DMODEL,
            pbqkv+l*1536,5,nullptr,qh,kh,vth,DMODEL,0.f,nullptr);

        flash_kernel<<<dim3(4,BH),256,FSMEM>>>(qh,kh,vth,chh,scale);

        gemm_f16<2><<<dim3(4,64),256,GSMEM2>>>(chh,DMODEL,woh+w5,DMODEL,bo+l*DMODEL,3,
            ptmp,nullptr,nullptr,nullptr,DMODEL,0.f,nullptr);
        ln_kernel<<<MTOK,128>>>(px,ptmp,n1s+l*DMODEL,n1b+l*DMODEL,px,xh);

        gemm_f16<4><<<dim3(16,32),256,GSMEM4>>>(xh,DMODEL,f1h+wf1,DMODEL,ffb1+l*DFF,1,
            nullptr,fhh,nullptr,nullptr,DFF,0.f,nullptr);
        gemm_f16<2><<<dim3(4,64),256,GSMEM2>>>(fhh,DFF,f2h+wf2,DFF,ffb2+l*DMODEL,3,
            ptmp,nullptr,nullptr,nullptr,DMODEL,0.f,nullptr);

        float* lnout=(l==NLAYER-1)?out:px;
        ln_kernel<<<MTOK,128>>>(px,ptmp,n2s+l*DMODEL,n2b+l*DMODEL,lnout,xh);
    }
}